// round 3
// baseline (speedup 1.0000x reference)
#include <cuda_runtime.h>
#include <cuda_bf16.h>
#include <cstdint>

// ---------------------------------------------------------------------------
// AdaptiveSoftmax
//   inputs (metadata order):
//     0: w_in     [4096,1024]  f32
//     1: target   [4096]       i32 (JAX x64 disabled -> int64 request demotes)
//     2: head_w   [2002,1024]  f32
//     3: head_b   [2002]       f32
//     4: tail0_w1 [1024,1024]  f32
//     5: tail0_w2 [8000,1024]  f32
//     6: tail1_w1 [256,1024]   f32
//     7: tail1_w2 [40000,256]  f32
//   output: scalar f32 loss
// ---------------------------------------------------------------------------

#define N_TOK 4096
#define K_IN  1024

// scratch: device globals only; never touched by host APIs
__device__ __align__(16) float d_logits[(size_t)N_TOK * 40000];
__device__ __align__(16) float d_h0[(size_t)N_TOK * 1024];
__device__ __align__(16) float d_h1[(size_t)N_TOK * 256];
__device__ float d_nll[N_TOK];
__device__ int   d_idx0[N_TOK];
__device__ int   d_idx1[N_TOK];
__device__ int   d_cnt0;
__device__ int   d_cnt1;

// ---------------------------------------------------------------------------
__global__ void init_kernel() {
    int i = blockIdx.x * blockDim.x + threadIdx.x;
    if (i < N_TOK) d_nll[i] = 0.0f;
    if (i == 0) { d_cnt0 = 0; d_cnt1 = 0; }
}

__global__ void gather_kernel(const int* __restrict__ target) {
    int i = blockIdx.x * blockDim.x + threadIdx.x;
    if (i >= N_TOK) return;
    int t = target[i];
    if (t >= 2000 && t < 10000) {
        int p = atomicAdd(&d_cnt0, 1);
        if (p < N_TOK) d_idx0[p] = i;
    } else if (t >= 10000 && t < 50000) {
        int p = atomicAdd(&d_cnt1, 1);
        if (p < N_TOK) d_idx1[p] = i;
    }
}

// ---------------------------------------------------------------------------
// C[m,n] = sum_k A[row(m),k] * B[n,k] (+ bias[n])
// A selected by a_sel: 0=Aparam (w_in), 1=d_h0, 2=d_h1
// C selected by c_sel: 0=d_logits, 1=d_h0, 2=d_h1
// idx_sel: 0 identity, 1 d_idx0, 2 d_idx1 (A row gather)
// cnt_sel: 0 N_TOK, 1 d_cnt0, 2 d_cnt1 (effective M)
// ---------------------------------------------------------------------------
#define BM 64
#define BN 64
#define BK 16

__global__ __launch_bounds__(256)
void gemm_tn(const float* __restrict__ Aparam, const float* __restrict__ B,
             const float* __restrict__ bias,
             int a_sel, int c_sel, int idx_sel, int cnt_sel, int N, int K) {
    int cnt = (cnt_sel == 0) ? N_TOK : ((cnt_sel == 1) ? d_cnt0 : d_cnt1);
    if (cnt > N_TOK) cnt = N_TOK;
    int m0 = blockIdx.y * BM;
    int n0 = blockIdx.x * BN;
    if (m0 >= cnt) return;

    const float* A = (a_sel == 0) ? Aparam : ((a_sel == 1) ? d_h0 : d_h1);
    float*       C = (c_sel == 0) ? d_logits : ((c_sel == 1) ? d_h0 : d_h1);

    __shared__ __align__(16) float As[BK][BM];
    __shared__ __align__(16) float Bs[BK][BN];

    int tid = threadIdx.x;
    int tx = tid & 15;   // -> n
    int ty = tid >> 4;   // -> m

    float acc[4][4];
#pragma unroll
    for (int i = 0; i < 4; i++)
#pragma unroll
        for (int j = 0; j < 4; j++) acc[i][j] = 0.0f;

    int lr = tid >> 2;          // 0..63 load row
    int lc = (tid & 3) * 4;     // 0,4,8,12 load col (k)

    for (int k0 = 0; k0 < K; k0 += BK) {
        {
            int m = m0 + lr;
            float4 v = make_float4(0.f, 0.f, 0.f, 0.f);
            if (m < cnt) {
                int row = (idx_sel == 0) ? m
                        : ((idx_sel == 1) ? d_idx0[m] : d_idx1[m]);
                row = min(max(row, 0), N_TOK - 1);
                v = *reinterpret_cast<const float4*>(A + (size_t)row * K + k0 + lc);
            }
            As[lc + 0][lr] = v.x;
            As[lc + 1][lr] = v.y;
            As[lc + 2][lr] = v.z;
            As[lc + 3][lr] = v.w;
        }
        {
            int n = n0 + lr;
            float4 v = make_float4(0.f, 0.f, 0.f, 0.f);
            if (n < N)
                v = *reinterpret_cast<const float4*>(B + (size_t)n * K + k0 + lc);
            Bs[lc + 0][lr] = v.x;
            Bs[lc + 1][lr] = v.y;
            Bs[lc + 2][lr] = v.z;
            Bs[lc + 3][lr] = v.w;
        }
        __syncthreads();

#pragma unroll
        for (int k = 0; k < BK; k++) {
            float4 a = *reinterpret_cast<const float4*>(&As[k][ty * 4]);
            float4 b = *reinterpret_cast<const float4*>(&Bs[k][tx * 4]);
            float av[4] = {a.x, a.y, a.z, a.w};
            float bv[4] = {b.x, b.y, b.z, b.w};
#pragma unroll
            for (int i = 0; i < 4; i++)
#pragma unroll
                for (int j = 0; j < 4; j++) acc[i][j] = fmaf(av[i], bv[j], acc[i][j]);
        }
        __syncthreads();
    }

#pragma unroll
    for (int i = 0; i < 4; i++) {
        int m = m0 + ty * 4 + i;
        if (m >= cnt) continue;
#pragma unroll
        for (int j = 0; j < 4; j++) {
            int n = n0 + tx * 4 + j;
            if (n < N) {
                float v = acc[i][j];
                if (bias) v += bias[n];
                C[(size_t)m * N + n] = v;
            }
        }
    }
}

// ---------------------------------------------------------------------------
// Per-token CE over compact logits [cnt, N] in d_logits.
// mode 0: head (first_target mapping). mode 1: tail (label = clamp(t - lo)).
// ---------------------------------------------------------------------------
__global__ __launch_bounds__(256)
void ce_kernel(int N, const int* __restrict__ target,
               int idx_sel, int cnt_sel, int lo, int mode) {
    int cnt = (cnt_sel == 0) ? N_TOK : ((cnt_sel == 1) ? d_cnt0 : d_cnt1);
    if (cnt > N_TOK) cnt = N_TOK;
    int b = blockIdx.x;
    if (b >= cnt) return;
    int tok = (idx_sel == 0) ? b : ((idx_sel == 1) ? d_idx0[b] : d_idx1[b]);
    tok = min(max(tok, 0), N_TOK - 1);
    const float* row = d_logits + (size_t)b * N;

    int t = target[tok];
    int label;
    if (mode == 0) {
        label = (t >= 2000 && t < 10000) ? 2000
              : ((t >= 10000 && t < 50000) ? 2001 : t);
    } else {
        label = t - lo;
    }
    label = min(max(label, 0), N - 1);

    __shared__ float sred[256];

    float m = -1e30f;
    for (int j = threadIdx.x; j < N; j += 256) m = fmaxf(m, row[j]);
    sred[threadIdx.x] = m;
    __syncthreads();
#pragma unroll
    for (int s = 128; s > 0; s >>= 1) {
        if (threadIdx.x < s)
            sred[threadIdx.x] = fmaxf(sred[threadIdx.x], sred[threadIdx.x + s]);
        __syncthreads();
    }
    float gm = sred[0];
    __syncthreads();

    float acc = 0.0f;
    for (int j = threadIdx.x; j < N; j += 256) acc += __expf(row[j] - gm);
    sred[threadIdx.x] = acc;
    __syncthreads();
#pragma unroll
    for (int s = 128; s > 0; s >>= 1) {
        if (threadIdx.x < s) sred[threadIdx.x] += sred[threadIdx.x + s];
        __syncthreads();
    }

    if (threadIdx.x == 0) {
        float nll = logf(sred[0]) + gm - row[label];
        d_nll[tok] += nll;   // kernels run sequentially; per-token accumulation
    }
}

__global__ void reduce_kernel(float* __restrict__ out) {
    __shared__ float s[1024];
    float a = 0.0f;
    for (int i = threadIdx.x; i < N_TOK; i += 1024) a += d_nll[i];
    s[threadIdx.x] = a;
    __syncthreads();
#pragma unroll
    for (int k = 512; k > 0; k >>= 1) {
        if (threadIdx.x < k) s[threadIdx.x] += s[threadIdx.x + k];
        __syncthreads();
    }
    if (threadIdx.x == 0) out[0] = s[0] / (float)N_TOK;
}

// ---------------------------------------------------------------------------
extern "C" void kernel_launch(void* const* d_in, const int* in_sizes, int n_in,
                              void* d_out, int out_size) {
    const float* w_in   = (const float*)d_in[0];
    const int*   target = (const int*)d_in[1];
    const float* head_w = (const float*)d_in[2];
    const float* head_b = (const float*)d_in[3];
    const float* t0w1   = (const float*)d_in[4];
    const float* t0w2   = (const float*)d_in[5];
    const float* t1w1   = (const float*)d_in[6];
    const float* t1w2   = (const float*)d_in[7];
    float* out = (float*)d_out;

    init_kernel<<<(N_TOK + 255) / 256, 256>>>();
    gather_kernel<<<(N_TOK + 255) / 256, 256>>>(target);

    // ---- head: logits = w_in @ head_w.T + head_b; CE with first_target ----
    {
        dim3 g((2002 + BN - 1) / BN, N_TOK / BM);
        gemm_tn<<<g, 256>>>(w_in, head_w, head_b,
                            /*a*/0, /*c*/0, /*idx*/0, /*cnt*/0, 2002, K_IN);
        ce_kernel<<<N_TOK, 256>>>(2002, target, 0, 0, 0, /*mode*/0);
    }

    // ---- tail0 (targets in [2000,10000)), gathered tokens only ----
    {
        dim3 g1(1024 / BN, N_TOK / BM);
        gemm_tn<<<g1, 256>>>(w_in, t0w1, nullptr,
                             /*a*/0, /*c*/1, /*idx*/1, /*cnt*/1, 1024, K_IN);
        dim3 g2((8000 + BN - 1) / BN, N_TOK / BM);
        gemm_tn<<<g2, 256>>>(nullptr, t0w2, nullptr,
                             /*a*/1, /*c*/0, /*idx*/0, /*cnt*/1, 8000, 1024);
        ce_kernel<<<N_TOK, 256>>>(8000, target, 1, 1, 2000, /*mode*/1);
    }

    // ---- tail1 (targets in [10000,50000)), gathered tokens only ----
    {
        dim3 g1(256 / BN, N_TOK / BM);
        gemm_tn<<<g1, 256>>>(w_in, t1w1, nullptr,
                             /*a*/0, /*c*/2, /*idx*/2, /*cnt*/2, 256, K_IN);
        dim3 g2((40000 + BN - 1) / BN, N_TOK / BM);
        gemm_tn<<<g2, 256>>>(nullptr, t1w2, nullptr,
                             /*a*/2, /*c*/0, /*idx*/0, /*cnt*/2, 40000, 256);
        ce_kernel<<<N_TOK, 256>>>(40000, target, 2, 2, 10000, /*mode*/1);
    }

    reduce_kernel<<<1, 1024>>>(out);
}

// round 5
// speedup vs baseline: 2.3310x; 2.3310x over previous
#include <cuda_runtime.h>
#include <cuda_bf16.h>
#include <cstdint>

// ---------------------------------------------------------------------------
// AdaptiveSoftmax — tf32 mma.sync GEMMs + online-softmax CE
//   0: w_in [4096,1024] f32   1: target [4096] i32
//   2: head_w [2002,1024] f32 3: head_b [2002] f32
//   4: tail0_w1 [1024,1024]   5: tail0_w2 [8000,1024]
//   6: tail1_w1 [256,1024]    7: tail1_w2 [40000,256]
//   out: scalar f32 loss
// ---------------------------------------------------------------------------

#define N_TOK 4096

__device__ __align__(16) float d_logits[(size_t)N_TOK * 40000];
__device__ __align__(16) float d_h0f[(size_t)N_TOK * 1024];
__device__ __align__(16) float d_h1f[(size_t)N_TOK * 256];
__device__ float d_nll[N_TOK];
__device__ int   d_idx0[N_TOK];
__device__ int   d_idx1[N_TOK];
__device__ int   d_cnt0;
__device__ int   d_cnt1;

// ---------------------------------------------------------------------------
__global__ void init_kernel() {
    int i = blockIdx.x * blockDim.x + threadIdx.x;
    if (i < N_TOK) d_nll[i] = 0.0f;
    if (i == 0) { d_cnt0 = 0; d_cnt1 = 0; }
}

__global__ void gather_kernel(const int* __restrict__ target) {
    int i = blockIdx.x * blockDim.x + threadIdx.x;
    if (i >= N_TOK) return;
    int t = target[i];
    if (t >= 2000 && t < 10000) {
        int p = atomicAdd(&d_cnt0, 1);
        if (p < N_TOK) d_idx0[p] = i;
    } else if (t >= 10000 && t < 50000) {
        int p = atomicAdd(&d_cnt1, 1);
        if (p < N_TOK) d_idx1[p] = i;
    }
}

// ---------------------------------------------------------------------------
__device__ __forceinline__ float f2tf32(float x) {
    uint32_t r;
    asm("cvt.rna.tf32.f32 %0, %1;" : "=r"(r) : "f"(x));
    return __uint_as_float(r);
}

__device__ __forceinline__ void mma_tf32(float* d, const uint32_t* a,
                                         const uint32_t* b) {
    asm volatile(
        "mma.sync.aligned.m16n8k8.row.col.f32.tf32.tf32.f32 "
        "{%0,%1,%2,%3}, {%4,%5,%6,%7}, {%8,%9}, {%0,%1,%2,%3};"
        : "+f"(d[0]), "+f"(d[1]), "+f"(d[2]), "+f"(d[3])
        : "r"(a[0]), "r"(a[1]), "r"(a[2]), "r"(a[3]), "r"(b[0]), "r"(b[1]));
}

// ---------------------------------------------------------------------------
// C[m,n] = sum_k A[row(m),k] * B[n,k] (+ bias[n])
// Block 128x128x32, 256 thr, 8 warps (2m x 4n), warp tile 64x32 (m16n8k8 4x4).
// smem: single buffer, K-pair permuted layout (cols k,k+4 adjacent) so
// fragment loads are LDS.64, stride 40 floats (conflict-free).
// a_sel: 0=Aparam 1=d_h0f 2=d_h1f ; c_sel: 0=d_logits 1=d_h0f 2=d_h1f
// idx_sel: 0 identity, 1 d_idx0, 2 d_idx1 ; cnt_sel: 0 N_TOK, 1 cnt0, 2 cnt1
// ---------------------------------------------------------------------------
#define SS 40   // smem row stride in floats

__global__ __launch_bounds__(256)
void gemm_mma(const float* __restrict__ Aparam, const float* __restrict__ B,
              const float* __restrict__ bias,
              int a_sel, int c_sel, int idx_sel, int cnt_sel, int N, int K) {
    int cnt = (cnt_sel == 0) ? N_TOK : ((cnt_sel == 1) ? d_cnt0 : d_cnt1);
    if (cnt > N_TOK) cnt = N_TOK;
    int m0 = blockIdx.y * 128;
    int n0 = blockIdx.x * 128;
    if (m0 >= cnt) return;

    const float* A = (a_sel == 0) ? Aparam : ((a_sel == 1) ? d_h0f : d_h1f);
    float*       C = (c_sel == 0) ? d_logits : ((c_sel == 1) ? d_h0f : d_h1f);

    __shared__ __align__(16) float As[128 * SS];
    __shared__ __align__(16) float Bs[128 * SS];

    int tid  = threadIdx.x;
    int lane = tid & 31;
    int warp = tid >> 5;
    int wm = warp & 1;    // 0..1  -> m offset wm*64
    int wn = warp >> 1;   // 0..3  -> n offset wn*32

    // ---- gmem load setup: thread loads 4 float4 per matrix per K-tile ----
    int rl = tid >> 3;            // 0..31 (rows rl, rl+32, rl+64, rl+96)
    int j  = tid & 7;             // float4 index within 32-col tile
    int stsCol = (j >> 1) * 8 + (j & 1);   // permuted base col

    const float* aPtr[4]; bool aOk[4];
    const float* bPtr[4]; bool bOk[4];
#pragma unroll
    for (int t = 0; t < 4; t++) {
        int m = m0 + rl + t * 32;
        aOk[t] = (m < cnt);
        int row = m;
        if (aOk[t] && idx_sel != 0)
            row = (idx_sel == 1) ? d_idx0[m] : d_idx1[m];
        row = min(max(row, 0), N_TOK - 1);
        aPtr[t] = A + (size_t)row * K + j * 4;

        int n = n0 + rl + t * 32;
        bOk[t] = (n < N);
        bPtr[t] = B + (size_t)min(n, N - 1) * K + j * 4;
    }

    float acc[4][4][4];
#pragma unroll
    for (int mt = 0; mt < 4; mt++)
#pragma unroll
        for (int nt = 0; nt < 4; nt++)
#pragma unroll
            for (int e = 0; e < 4; e++) acc[mt][nt][e] = 0.0f;

    int aRow = wm * 64 + (lane >> 2);
    int bRow = wn * 32 + (lane >> 2);
    int qk   = (lane & 3) * 2;

    float4 aReg[4], bReg[4];
    const float4 z4 = make_float4(0.f, 0.f, 0.f, 0.f);

    // prefetch tile 0
#pragma unroll
    for (int t = 0; t < 4; t++) {
        aReg[t] = aOk[t] ? *reinterpret_cast<const float4*>(aPtr[t]) : z4;
        bReg[t] = bOk[t] ? *reinterpret_cast<const float4*>(bPtr[t]) : z4;
    }

    int nk = K >> 5;
    for (int kt = 0; kt < nk; kt++) {
        // store prefetched tile to smem (tf32-rounded, permuted cols)
#pragma unroll
        for (int t = 0; t < 4; t++) {
            int ro = (rl + t * 32) * SS + stsCol;
            As[ro + 0] = f2tf32(aReg[t].x);
            As[ro + 2] = f2tf32(aReg[t].y);
            As[ro + 4] = f2tf32(aReg[t].z);
            As[ro + 6] = f2tf32(aReg[t].w);
            Bs[ro + 0] = f2tf32(bReg[t].x);
            Bs[ro + 2] = f2tf32(bReg[t].y);
            Bs[ro + 4] = f2tf32(bReg[t].z);
            Bs[ro + 6] = f2tf32(bReg[t].w);
        }
        __syncthreads();

        // prefetch next tile
        if (kt + 1 < nk) {
            int off = (kt + 1) * 32;
#pragma unroll
            for (int t = 0; t < 4; t++) {
                aReg[t] = aOk[t] ? *reinterpret_cast<const float4*>(aPtr[t] + off) : z4;
                bReg[t] = bOk[t] ? *reinterpret_cast<const float4*>(bPtr[t] + off) : z4;
            }
        }

        // compute on current tile
#pragma unroll
        for (int ks = 0; ks < 4; ks++) {
            int kk = ks * 8 + qk;
            uint32_t afr[4][4], bfr[4][2];
#pragma unroll
            for (int mt = 0; mt < 4; mt++) {
                float2 x = *reinterpret_cast<const float2*>(&As[(aRow + mt * 16) * SS + kk]);
                float2 y = *reinterpret_cast<const float2*>(&As[(aRow + mt * 16 + 8) * SS + kk]);
                afr[mt][0] = __float_as_uint(x.x);
                afr[mt][1] = __float_as_uint(y.x);
                afr[mt][2] = __float_as_uint(x.y);
                afr[mt][3] = __float_as_uint(y.y);
            }
#pragma unroll
            for (int nt = 0; nt < 4; nt++) {
                float2 x = *reinterpret_cast<const float2*>(&Bs[(bRow + nt * 8) * SS + kk]);
                bfr[nt][0] = __float_as_uint(x.x);
                bfr[nt][1] = __float_as_uint(x.y);
            }
#pragma unroll
            for (int mt = 0; mt < 4; mt++)
#pragma unroll
                for (int nt = 0; nt < 4; nt++)
                    mma_tf32(acc[mt][nt], afr[mt], bfr[nt]);
        }
        __syncthreads();
    }

    // ---- epilogue ----
#pragma unroll
    for (int mt = 0; mt < 4; mt++) {
        int r0 = m0 + wm * 64 + mt * 16 + (lane >> 2);
        int r1 = r0 + 8;
#pragma unroll
        for (int nt = 0; nt < 4; nt++) {
            int cb = n0 + wn * 32 + nt * 8 + (lane & 3) * 2;
            float b0 = 0.f, b1 = 0.f;
            if (bias) {
                if (cb < N)     b0 = bias[cb];
                if (cb + 1 < N) b1 = bias[cb + 1];
            }
            if (r0 < cnt) {
                if (cb < N)     C[(size_t)r0 * N + cb]     = acc[mt][nt][0] + b0;
                if (cb + 1 < N) C[(size_t)r0 * N + cb + 1] = acc[mt][nt][1] + b1;
            }
            if (r1 < cnt) {
                if (cb < N)     C[(size_t)r1 * N + cb]     = acc[mt][nt][2] + b0;
                if (cb + 1 < N) C[(size_t)r1 * N + cb + 1] = acc[mt][nt][3] + b1;
            }
        }
    }
}

// ---------------------------------------------------------------------------
// Online single-pass softmax CE over compact logits [cnt, N] in d_logits.
// ---------------------------------------------------------------------------
__global__ __launch_bounds__(256)
void ce_kernel(int N, const int* __restrict__ target,
               int idx_sel, int cnt_sel, int lo, int mode) {
    int cnt = (cnt_sel == 0) ? N_TOK : ((cnt_sel == 1) ? d_cnt0 : d_cnt1);
    if (cnt > N_TOK) cnt = N_TOK;
    int b = blockIdx.x;
    if (b >= cnt) return;
    int tok = (idx_sel == 0) ? b : ((idx_sel == 1) ? d_idx0[b] : d_idx1[b]);
    tok = min(max(tok, 0), N_TOK - 1);
    const float* row = d_logits + (size_t)b * N;

    int t = target[tok];
    int label;
    if (mode == 0) {
        label = (t >= 2000 && t < 10000) ? 2000
              : ((t >= 10000 && t < 50000) ? 2001 : t);
    } else {
        label = t - lo;
    }
    label = min(max(label, 0), N - 1);

    // online max/sum per thread
    float mx = -1e30f, s = 0.0f;
    for (int jj = threadIdx.x; jj < N; jj += 256) {
        float x = row[jj];
        if (x <= mx) {
            s += __expf(x - mx);
        } else {
            s = s * __expf(mx - x) + 1.0f;
            mx = x;
        }
    }

    __shared__ float sm[256], ss[256];
    sm[threadIdx.x] = mx;
    ss[threadIdx.x] = s;
    __syncthreads();
    // block max
#pragma unroll
    for (int st = 128; st > 0; st >>= 1) {
        if (threadIdx.x < st)
            sm[threadIdx.x] = fmaxf(sm[threadIdx.x], sm[threadIdx.x + st]);
        __syncthreads();
    }
    float gm = sm[0];
    __syncthreads();
    // rescale partial sums and block sum
    ss[threadIdx.x] = ss[threadIdx.x] * __expf(mx - gm);
    __syncthreads();
#pragma unroll
    for (int st = 128; st > 0; st >>= 1) {
        if (threadIdx.x < st) ss[threadIdx.x] += ss[threadIdx.x + st];
        __syncthreads();
    }

    if (threadIdx.x == 0) {
        float nll = logf(ss[0]) + gm - row[label];
        d_nll[tok] += nll;
    }
}

__global__ void reduce_kernel(float* __restrict__ out) {
    __shared__ float s[1024];
    float a = 0.0f;
    for (int i = threadIdx.x; i < N_TOK; i += 1024) a += d_nll[i];
    s[threadIdx.x] = a;
    __syncthreads();
#pragma unroll
    for (int k = 512; k > 0; k >>= 1) {
        if (threadIdx.x < k) s[threadIdx.x] += s[threadIdx.x + k];
        __syncthreads();
    }
    if (threadIdx.x == 0) out[0] = s[0] / (float)N_TOK;
}

// ---------------------------------------------------------------------------
extern "C" void kernel_launch(void* const* d_in, const int* in_sizes, int n_in,
                              void* d_out, int out_size) {
    const float* w_in   = (const float*)d_in[0];
    const int*   target = (const int*)d_in[1];
    const float* head_w = (const float*)d_in[2];
    const float* head_b = (const float*)d_in[3];
    const float* t0w1   = (const float*)d_in[4];
    const float* t0w2   = (const float*)d_in[5];
    const float* t1w1   = (const float*)d_in[6];
    const float* t1w2   = (const float*)d_in[7];
    float* out = (float*)d_out;

    init_kernel<<<(N_TOK + 255) / 256, 256>>>();
    gather_kernel<<<(N_TOK + 255) / 256, 256>>>(target);

    // ---- head: logits = w_in @ head_w.T + head_b ----
    {
        dim3 g((2002 + 127) / 128, N_TOK / 128);
        gemm_mma<<<g, 256>>>(w_in, head_w, head_b, 0, 0, 0, 0, 2002, 1024);
        ce_kernel<<<N_TOK, 256>>>(2002, target, 0, 0, 0, /*mode*/0);
    }
    // ---- tail0 (targets in [2000,10000)) ----
    {
        dim3 g1(1024 / 128, N_TOK / 128);
        gemm_mma<<<g1, 256>>>(w_in, t0w1, nullptr, 0, 1, 1, 1, 1024, 1024);
        dim3 g2((8000 + 127) / 128, N_TOK / 128);
        gemm_mma<<<g2, 256>>>(nullptr, t0w2, nullptr, 1, 0, 0, 1, 8000, 1024);
        ce_kernel<<<N_TOK, 256>>>(8000, target, 1, 1, 2000, /*mode*/1);
    }
    // ---- tail1 (targets in [10000,50000)) ----
    {
        dim3 g1(256 / 128, N_TOK / 128);
        gemm_mma<<<g1, 256>>>(w_in, t1w1, nullptr, 0, 2, 2, 2, 256, 1024);
        dim3 g2((40000 + 127) / 128, N_TOK / 128);
        gemm_mma<<<g2, 256>>>(nullptr, t1w2, nullptr, 2, 0, 0, 2, 40000, 256);
        ce_kernel<<<N_TOK, 256>>>(40000, target, 2, 2, 10000, /*mode*/1);
    }

    reduce_kernel<<<1, 1024>>>(out);
}

// round 6
// speedup vs baseline: 3.3863x; 1.4527x over previous
#include <cuda_runtime.h>
#include <cuda_fp16.h>
#include <cstdint>

// ---------------------------------------------------------------------------
// AdaptiveSoftmax — fp16 mma.sync (m16n8k16, f32 accum) GEMMs + online CE
//   0: w_in [4096,1024] f32   1: target [4096] i32
//   2: head_w [2002,1024] f32 3: head_b [2002] f32
//   4: tail0_w1 [1024,1024]   5: tail0_w2 [8000,1024]
//   6: tail1_w1 [256,1024]    7: tail1_w2 [40000,256]
//   out: scalar f32 loss
// ---------------------------------------------------------------------------

#define N_TOK 4096

__device__ __align__(16) float d_logits[(size_t)N_TOK * 40000];
__device__ __align__(16) float d_h0f[(size_t)N_TOK * 1024];
__device__ __align__(16) float d_h1f[(size_t)N_TOK * 256];
__device__ float d_nll[N_TOK];
__device__ int   d_idx0[N_TOK];
__device__ int   d_idx1[N_TOK];
__device__ int   d_cnt0;
__device__ int   d_cnt1;

// ---------------------------------------------------------------------------
__global__ void init_kernel() {
    int i = blockIdx.x * blockDim.x + threadIdx.x;
    if (i < N_TOK) d_nll[i] = 0.0f;
    if (i == 0) { d_cnt0 = 0; d_cnt1 = 0; }
}

__global__ void gather_kernel(const int* __restrict__ target) {
    int i = blockIdx.x * blockDim.x + threadIdx.x;
    if (i >= N_TOK) return;
    int t = target[i];
    if (t >= 2000 && t < 10000) {
        int p = atomicAdd(&d_cnt0, 1);
        if (p < N_TOK) d_idx0[p] = i;
    } else if (t >= 10000 && t < 50000) {
        int p = atomicAdd(&d_cnt1, 1);
        if (p < N_TOK) d_idx1[p] = i;
    }
}

// ---------------------------------------------------------------------------
__device__ __forceinline__ uint32_t pack_h2(float x, float y) {
    __half2 h = __floats2half2_rn(x, y);
    return *reinterpret_cast<uint32_t*>(&h);
}

__device__ __forceinline__ void mma_f16(float* d, const uint32_t* a,
                                        const uint32_t* b) {
    asm volatile(
        "mma.sync.aligned.m16n8k16.row.col.f32.f16.f16.f32 "
        "{%0,%1,%2,%3}, {%4,%5,%6,%7}, {%8,%9}, {%0,%1,%2,%3};"
        : "+f"(d[0]), "+f"(d[1]), "+f"(d[2]), "+f"(d[3])
        : "r"(a[0]), "r"(a[1]), "r"(a[2]), "r"(a[3]), "r"(b[0]), "r"(b[1]));
}

// kpair slot permutation within a K-tile (16 kpairs = 2 k16 groups of 8):
// within each group of 8 kpairs q: slot = (q&3)*2 + (q>>2), so kpairs t and
// t+4 (the two k-halves a lane needs) sit in adjacent slots -> one LDS.64.
__device__ __forceinline__ int slot_of(int p) {
    int g = p >> 3, q = p & 7;
    return g * 8 + (q & 3) * 2 + (q >> 2);
}

// ---------------------------------------------------------------------------
// C[m,n] = sum_k A[row(m),k] * B[n,k] (+ bias[n])
// Block 128x128x32(f32 k), 256 thr, 8 warps (2m x 4n), warp tile 64x32.
// fp16 m16n8k16, fp32 accum. smem: packed half2 kpair slots, 16 u32/row,
// XOR swizzle by 4*(row&3) -> conflict-free LDS.64 fragment loads.
// ---------------------------------------------------------------------------
__global__ __launch_bounds__(256)
void gemm_mma(const float* __restrict__ Aparam, const float* __restrict__ B,
              const float* __restrict__ bias,
              int a_sel, int c_sel, int idx_sel, int cnt_sel, int N, int K) {
    int cnt = (cnt_sel == 0) ? N_TOK : ((cnt_sel == 1) ? d_cnt0 : d_cnt1);
    if (cnt > N_TOK) cnt = N_TOK;
    int m0 = blockIdx.y * 128;
    int n0 = blockIdx.x * 128;
    if (m0 >= cnt) return;

    const float* A = (a_sel == 0) ? Aparam : ((a_sel == 1) ? d_h0f : d_h1f);
    float*       C = (c_sel == 0) ? d_logits : ((c_sel == 1) ? d_h0f : d_h1f);

    __shared__ __align__(16) uint32_t As[128 * 16];
    __shared__ __align__(16) uint32_t Bs[128 * 16];

    int tid  = threadIdx.x;
    int lane = tid & 31;
    int warp = tid >> 5;
    int wm = warp & 1;    // m offset wm*64
    int wn = warp >> 1;   // n offset wn*32

    // ---- gmem load setup: thread loads 4 float4 per matrix per K-tile ----
    int rl = tid >> 3;            // rows rl, rl+32, rl+64, rl+96
    int j  = tid & 7;             // float4 index (kpairs 2j, 2j+1)
    int s0 = slot_of(2 * j);
    int s1 = slot_of(2 * j + 1);
    int xmS = 4 * (rl & 3);       // row&3 invariant across t (+32)

    const float* aPtr[4]; bool aOk[4];
    const float* bPtr[4]; bool bOk[4];
#pragma unroll
    for (int t = 0; t < 4; t++) {
        int m = m0 + rl + t * 32;
        aOk[t] = (m < cnt);
        int row = m;
        if (aOk[t] && idx_sel != 0)
            row = (idx_sel == 1) ? d_idx0[m] : d_idx1[m];
        row = min(max(row, 0), N_TOK - 1);
        aPtr[t] = A + (size_t)row * K + j * 4;

        int n = n0 + rl + t * 32;
        bOk[t] = (n < N);
        bPtr[t] = B + (size_t)min(n, N - 1) * K + j * 4;
    }

    float acc[4][4][4];
#pragma unroll
    for (int mt = 0; mt < 4; mt++)
#pragma unroll
        for (int nt = 0; nt < 4; nt++)
#pragma unroll
            for (int e = 0; e < 4; e++) acc[mt][nt][e] = 0.0f;

    int gq  = lane >> 2;          // group id (row within 8)
    int tq  = lane & 3;
    int xmL = 4 * (gq & 3);       // fragment-load XOR mask

    float4 aReg[4], bReg[4];
    const float4 z4 = make_float4(0.f, 0.f, 0.f, 0.f);

    // prefetch tile 0
#pragma unroll
    for (int t = 0; t < 4; t++) {
        aReg[t] = aOk[t] ? *reinterpret_cast<const float4*>(aPtr[t]) : z4;
        bReg[t] = bOk[t] ? *reinterpret_cast<const float4*>(bPtr[t]) : z4;
    }

    int nk = K >> 5;
    for (int kt = 0; kt < nk; kt++) {
        // store prefetched tile (cvt f32->f16, packed pairs, swizzled slots)
#pragma unroll
        for (int t = 0; t < 4; t++) {
            int base = (rl + t * 32) * 16;
            As[base + (s0 ^ xmS)] = pack_h2(aReg[t].x, aReg[t].y);
            As[base + (s1 ^ xmS)] = pack_h2(aReg[t].z, aReg[t].w);
            Bs[base + (s0 ^ xmS)] = pack_h2(bReg[t].x, bReg[t].y);
            Bs[base + (s1 ^ xmS)] = pack_h2(bReg[t].z, bReg[t].w);
        }
        __syncthreads();

        // prefetch next tile
        if (kt + 1 < nk) {
            int off = (kt + 1) * 32;
#pragma unroll
            for (int t = 0; t < 4; t++) {
                aReg[t] = aOk[t] ? *reinterpret_cast<const float4*>(aPtr[t] + off) : z4;
                bReg[t] = bOk[t] ? *reinterpret_cast<const float4*>(bPtr[t] + off) : z4;
            }
        }

        // compute: 2 k16 steps per tile
#pragma unroll
        for (int ks = 0; ks < 2; ks++) {
            int sIdx = (ks * 8 + 2 * tq) ^ xmL;
            uint32_t afr[4][4], bfr[4][2];
#pragma unroll
            for (int mt = 0; mt < 4; mt++) {
                int ra = wm * 64 + mt * 16 + gq;
                uint2 lo = *reinterpret_cast<const uint2*>(&As[ra * 16 + sIdx]);
                uint2 hi = *reinterpret_cast<const uint2*>(&As[(ra + 8) * 16 + sIdx]);
                afr[mt][0] = lo.x;   // (g,   k<8)
                afr[mt][1] = hi.x;   // (g+8, k<8)
                afr[mt][2] = lo.y;   // (g,   k>=8)
                afr[mt][3] = hi.y;   // (g+8, k>=8)
            }
#pragma unroll
            for (int nt = 0; nt < 4; nt++) {
                int rb = wn * 32 + nt * 8 + gq;
                uint2 bb = *reinterpret_cast<const uint2*>(&Bs[rb * 16 + sIdx]);
                bfr[nt][0] = bb.x;
                bfr[nt][1] = bb.y;
            }
#pragma unroll
            for (int mt = 0; mt < 4; mt++)
#pragma unroll
                for (int nt = 0; nt < 4; nt++)
                    mma_f16(acc[mt][nt], afr[mt], bfr[nt]);
        }
        __syncthreads();
    }

    // ---- epilogue ----
#pragma unroll
    for (int mt = 0; mt < 4; mt++) {
        int r0 = m0 + wm * 64 + mt * 16 + gq;
        int r1 = r0 + 8;
#pragma unroll
        for (int nt = 0; nt < 4; nt++) {
            int cb = n0 + wn * 32 + nt * 8 + tq * 2;
            float b0 = 0.f, b1 = 0.f;
            if (bias) {
                if (cb < N)     b0 = bias[cb];
                if (cb + 1 < N) b1 = bias[cb + 1];
            }
            if (r0 < cnt) {
                if (cb < N)     C[(size_t)r0 * N + cb]     = acc[mt][nt][0] + b0;
                if (cb + 1 < N) C[(size_t)r0 * N + cb + 1] = acc[mt][nt][1] + b1;
            }
            if (r1 < cnt) {
                if (cb < N)     C[(size_t)r1 * N + cb]     = acc[mt][nt][2] + b0;
                if (cb + 1 < N) C[(size_t)r1 * N + cb + 1] = acc[mt][nt][3] + b1;
            }
        }
    }
}

// ---------------------------------------------------------------------------
// Online single-pass softmax CE over compact logits [cnt, N] in d_logits.
// ---------------------------------------------------------------------------
__global__ __launch_bounds__(256)
void ce_kernel(int N, const int* __restrict__ target,
               int idx_sel, int cnt_sel, int lo, int mode) {
    int cnt = (cnt_sel == 0) ? N_TOK : ((cnt_sel == 1) ? d_cnt0 : d_cnt1);
    if (cnt > N_TOK) cnt = N_TOK;
    int b = blockIdx.x;
    if (b >= cnt) return;
    int tok = (idx_sel == 0) ? b : ((idx_sel == 1) ? d_idx0[b] : d_idx1[b]);
    tok = min(max(tok, 0), N_TOK - 1);
    const float* row = d_logits + (size_t)b * N;

    int t = target[tok];
    int label;
    if (mode == 0) {
        label = (t >= 2000 && t < 10000) ? 2000
              : ((t >= 10000 && t < 50000) ? 2001 : t);
    } else {
        label = t - lo;
    }
    label = min(max(label, 0), N - 1);

    float mx = -1e30f, s = 0.0f;
    for (int jj = threadIdx.x; jj < N; jj += 256) {
        float x = row[jj];
        if (x <= mx) {
            s += __expf(x - mx);
        } else {
            s = s * __expf(mx - x) + 1.0f;
            mx = x;
        }
    }

    __shared__ float sm[256], ss[256];
    sm[threadIdx.x] = mx;
    ss[threadIdx.x] = s;
    __syncthreads();
#pragma unroll
    for (int st = 128; st > 0; st >>= 1) {
        if (threadIdx.x < st)
            sm[threadIdx.x] = fmaxf(sm[threadIdx.x], sm[threadIdx.x + st]);
        __syncthreads();
    }
    float gm = sm[0];
    __syncthreads();
    ss[threadIdx.x] = ss[threadIdx.x] * __expf(mx - gm);
    __syncthreads();
#pragma unroll
    for (int st = 128; st > 0; st >>= 1) {
        if (threadIdx.x < st) ss[threadIdx.x] += ss[threadIdx.x + st];
        __syncthreads();
    }

    if (threadIdx.x == 0) {
        float nll = logf(ss[0]) + gm - row[label];
        d_nll[tok] += nll;
    }
}

__global__ void reduce_kernel(float* __restrict__ out) {
    __shared__ float s[1024];
    float a = 0.0f;
    for (int i = threadIdx.x; i < N_TOK; i += 1024) a += d_nll[i];
    s[threadIdx.x] = a;
    __syncthreads();
#pragma unroll
    for (int k = 512; k > 0; k >>= 1) {
        if (threadIdx.x < k) s[threadIdx.x] += s[threadIdx.x + k];
        __syncthreads();
    }
    if (threadIdx.x == 0) out[0] = s[0] / (float)N_TOK;
}

// ---------------------------------------------------------------------------
extern "C" void kernel_launch(void* const* d_in, const int* in_sizes, int n_in,
                              void* d_out, int out_size) {
    const float* w_in   = (const float*)d_in[0];
    const int*   target = (const int*)d_in[1];
    const float* head_w = (const float*)d_in[2];
    const float* head_b = (const float*)d_in[3];
    const float* t0w1   = (const float*)d_in[4];
    const float* t0w2   = (const float*)d_in[5];
    const float* t1w1   = (const float*)d_in[6];
    const float* t1w2   = (const float*)d_in[7];
    float* out = (float*)d_out;

    init_kernel<<<(N_TOK + 255) / 256, 256>>>();
    gather_kernel<<<(N_TOK + 255) / 256, 256>>>(target);

    // ---- head: logits = w_in @ head_w.T + head_b ----
    {
        dim3 g((2002 + 127) / 128, N_TOK / 128);
        gemm_mma<<<g, 256>>>(w_in, head_w, head_b, 0, 0, 0, 0, 2002, 1024);
        ce_kernel<<<N_TOK, 256>>>(2002, target, 0, 0, 0, /*mode*/0);
    }
    // ---- tail0 (targets in [2000,10000)) ----
    {
        dim3 g1(1024 / 128, N_TOK / 128);
        gemm_mma<<<g1, 256>>>(w_in, t0w1, nullptr, 0, 1, 1, 1, 1024, 1024);
        dim3 g2((8000 + 127) / 128, N_TOK / 128);
        gemm_mma<<<g2, 256>>>(nullptr, t0w2, nullptr, 1, 0, 0, 1, 8000, 1024);
        ce_kernel<<<N_TOK, 256>>>(8000, target, 1, 1, 2000, /*mode*/1);
    }
    // ---- tail1 (targets in [10000,50000)) ----
    {
        dim3 g1(256 / 128, N_TOK / 128);
        gemm_mma<<<g1, 256>>>(w_in, t1w1, nullptr, 0, 2, 2, 2, 256, 1024);
        dim3 g2((40000 + 127) / 128, N_TOK / 128);
        gemm_mma<<<g2, 256>>>(nullptr, t1w2, nullptr, 2, 0, 0, 2, 40000, 256);
        ce_kernel<<<N_TOK, 256>>>(40000, target, 2, 2, 10000, /*mode*/1);
    }

    reduce_kernel<<<1, 1024>>>(out);
}

// round 7
// speedup vs baseline: 3.6653x; 1.0824x over previous
#include <cuda_runtime.h>
#include <cuda_fp16.h>
#include <cstdint>

// ---------------------------------------------------------------------------
// AdaptiveSoftmax — fp16 mma.sync GEMMs with fused-CE epilogue
//   0: w_in [4096,1024] f32   1: target [4096] i32
//   2: head_w [2002,1024] f32 3: head_b [2002] f32
//   4: tail0_w1 [1024,1024]   5: tail0_w2 [8000,1024]
//   6: tail1_w1 [256,1024]    7: tail1_w2 [40000,256]
//   out: scalar f32 loss
// ---------------------------------------------------------------------------

#define N_TOK 4096
#define PT_STRIDE 320   // max N tiles (313) rounded up

__device__ __align__(16) float  d_h0f[(size_t)N_TOK * 1024];
__device__ __align__(16) float  d_h1f[(size_t)N_TOK * 256];
__device__ __align__(16) float2 d_part[(size_t)N_TOK * PT_STRIDE];
__device__ float d_labv[N_TOK];
__device__ float d_nll[N_TOK];
__device__ int   d_labh[N_TOK];
__device__ int   d_lab0[N_TOK];
__device__ int   d_lab1[N_TOK];
__device__ int   d_idx0[N_TOK];
__device__ int   d_idx1[N_TOK];
__device__ int   d_cnt0;
__device__ int   d_cnt1;

// ---------------------------------------------------------------------------
__global__ void init_kernel() {
    if (threadIdx.x == 0) { d_cnt0 = 0; d_cnt1 = 0; }
}

__global__ void gather_kernel(const int* __restrict__ target) {
    int i = blockIdx.x * blockDim.x + threadIdx.x;
    if (i >= N_TOK) return;
    int t = target[i];
    int labh = t;
    if (t >= 2000 && t < 10000) {
        labh = 2000;
        int p = atomicAdd(&d_cnt0, 1);
        if (p < N_TOK) { d_idx0[p] = i; d_lab0[p] = t - 2000; }
    } else if (t >= 10000 && t < 50000) {
        labh = 2001;
        int p = atomicAdd(&d_cnt1, 1);
        if (p < N_TOK) { d_idx1[p] = i; d_lab1[p] = t - 10000; }
    }
    d_labh[i] = min(max(labh, 0), 2001);
}

// ---------------------------------------------------------------------------
__device__ __forceinline__ uint32_t pack_h2(float x, float y) {
    __half2 h = __floats2half2_rn(x, y);
    return *reinterpret_cast<uint32_t*>(&h);
}

__device__ __forceinline__ void mma_f16(float* d, const uint32_t* a,
                                        const uint32_t* b) {
    asm volatile(
        "mma.sync.aligned.m16n8k16.row.col.f32.f16.f16.f32 "
        "{%0,%1,%2,%3}, {%4,%5,%6,%7}, {%8,%9}, {%0,%1,%2,%3};"
        : "+f"(d[0]), "+f"(d[1]), "+f"(d[2]), "+f"(d[3])
        : "r"(a[0]), "r"(a[1]), "r"(a[2]), "r"(a[3]), "r"(b[0]), "r"(b[1]));
}

__device__ __forceinline__ int slot_of(int p) {
    int g = p >> 3, q = p & 7;
    return g * 8 + (q & 3) * 2 + (q >> 2);
}

// online merge helper: (mx,sm) <- (mx,sm) merge (om,os)
__device__ __forceinline__ void ol_merge(float& mx, float& sm, float om, float os) {
    float nm = fmaxf(mx, om);
    sm = sm * __expf(mx - nm) + os * __expf(om - nm);
    mx = nm;
}

// ---------------------------------------------------------------------------
// C[m,n] = sum_k A[row(m),k] * B[n,k] (+ bias[n])
// Block 128x128x32, 256 thr, 8 warps (2m x 4n), warp tile 64x32, m16n8k16.
// ce_mode==0: write C (d_h0f / d_h1f).  ce_mode==1: fused CE — per-row
// (max, sum(exp)) partials to d_part[m*PT_STRIDE + tileN], label logit to
// d_labv[m]; no logits materialized.
// ---------------------------------------------------------------------------
__global__ __launch_bounds__(256)
void gemm_mma(const float* __restrict__ Aparam, const float* __restrict__ B,
              const float* __restrict__ bias,
              int a_sel, int c_sel, int idx_sel, int cnt_sel, int N, int K,
              int ce_mode) {
    int cnt = (cnt_sel == 0) ? N_TOK : ((cnt_sel == 1) ? d_cnt0 : d_cnt1);
    if (cnt > N_TOK) cnt = N_TOK;
    int m0 = blockIdx.y * 128;
    int n0 = blockIdx.x * 128;
    if (m0 >= cnt) return;

    const float* A = (a_sel == 0) ? Aparam : ((a_sel == 1) ? d_h0f : d_h1f);
    float*       C = (c_sel == 1) ? d_h0f : d_h1f;

    __shared__ __align__(16) uint32_t As[128 * 16];
    __shared__ __align__(16) uint32_t Bs[128 * 16];
    __shared__ float2 spart[128][4];

    int tid  = threadIdx.x;
    int lane = tid & 31;
    int warp = tid >> 5;
    int wm = warp & 1;
    int wn = warp >> 1;

    int rl = tid >> 3;
    int j  = tid & 7;
    int s0 = slot_of(2 * j);
    int s1 = slot_of(2 * j + 1);
    int xmS = 4 * (rl & 3);

    const float* aPtr[4]; bool aOk[4];
    const float* bPtr[4]; bool bOk[4];
#pragma unroll
    for (int t = 0; t < 4; t++) {
        int m = m0 + rl + t * 32;
        aOk[t] = (m < cnt);
        int row = m;
        if (aOk[t] && idx_sel != 0)
            row = (idx_sel == 1) ? d_idx0[m] : d_idx1[m];
        row = min(max(row, 0), N_TOK - 1);
        aPtr[t] = A + (size_t)row * K + j * 4;

        int n = n0 + rl + t * 32;
        bOk[t] = (n < N);
        bPtr[t] = B + (size_t)min(n, N - 1) * K + j * 4;
    }

    float acc[4][4][4];
#pragma unroll
    for (int mt = 0; mt < 4; mt++)
#pragma unroll
        for (int nt = 0; nt < 4; nt++)
#pragma unroll
            for (int e = 0; e < 4; e++) acc[mt][nt][e] = 0.0f;

    int gq  = lane >> 2;
    int tq  = lane & 3;
    int xmL = 4 * (gq & 3);

    float4 aReg[4], bReg[4];
    const float4 z4 = make_float4(0.f, 0.f, 0.f, 0.f);

#pragma unroll
    for (int t = 0; t < 4; t++) {
        aReg[t] = aOk[t] ? *reinterpret_cast<const float4*>(aPtr[t]) : z4;
        bReg[t] = bOk[t] ? *reinterpret_cast<const float4*>(bPtr[t]) : z4;
    }

    int nk = K >> 5;
    for (int kt = 0; kt < nk; kt++) {
#pragma unroll
        for (int t = 0; t < 4; t++) {
            int base = (rl + t * 32) * 16;
            As[base + (s0 ^ xmS)] = pack_h2(aReg[t].x, aReg[t].y);
            As[base + (s1 ^ xmS)] = pack_h2(aReg[t].z, aReg[t].w);
            Bs[base + (s0 ^ xmS)] = pack_h2(bReg[t].x, bReg[t].y);
            Bs[base + (s1 ^ xmS)] = pack_h2(bReg[t].z, bReg[t].w);
        }
        __syncthreads();

        if (kt + 1 < nk) {
            int off = (kt + 1) * 32;
#pragma unroll
            for (int t = 0; t < 4; t++) {
                aReg[t] = aOk[t] ? *reinterpret_cast<const float4*>(aPtr[t] + off) : z4;
                bReg[t] = bOk[t] ? *reinterpret_cast<const float4*>(bPtr[t] + off) : z4;
            }
        }

#pragma unroll
        for (int ks = 0; ks < 2; ks++) {
            int sIdx = (ks * 8 + 2 * tq) ^ xmL;
            uint32_t afr[4][4], bfr[4][2];
#pragma unroll
            for (int mt = 0; mt < 4; mt++) {
                int ra = wm * 64 + mt * 16 + gq;
                uint2 lo = *reinterpret_cast<const uint2*>(&As[ra * 16 + sIdx]);
                uint2 hi = *reinterpret_cast<const uint2*>(&As[(ra + 8) * 16 + sIdx]);
                afr[mt][0] = lo.x; afr[mt][1] = hi.x;
                afr[mt][2] = lo.y; afr[mt][3] = hi.y;
            }
#pragma unroll
            for (int nt = 0; nt < 4; nt++) {
                int rb = wn * 32 + nt * 8 + gq;
                uint2 bb = *reinterpret_cast<const uint2*>(&Bs[rb * 16 + sIdx]);
                bfr[nt][0] = bb.x; bfr[nt][1] = bb.y;
            }
#pragma unroll
            for (int mt = 0; mt < 4; mt++)
#pragma unroll
                for (int nt = 0; nt < 4; nt++)
                    mma_f16(acc[mt][nt], afr[mt], bfr[nt]);
        }
        __syncthreads();
    }

    if (ce_mode) {
        // ---- fused CE epilogue: per-row online (max, sum), label capture ----
        const int* labarr = (idx_sel == 0) ? d_labh
                          : ((idx_sel == 1) ? d_lab0 : d_lab1);
#pragma unroll
        for (int mt = 0; mt < 4; mt++) {
#pragma unroll
            for (int h = 0; h < 2; h++) {
                int rloc = wm * 64 + mt * 16 + gq + h * 8;
                int m = m0 + rloc;
                bool ok = (m < cnt);
                int lab = ok ? labarr[m] : -1;
                float mx = -1e30f, sm = 0.f;
#pragma unroll
                for (int nt = 0; nt < 4; nt++) {
#pragma unroll
                    for (int e = 0; e < 2; e++) {
                        int col = n0 + wn * 32 + nt * 8 + tq * 2 + e;
                        if (col < N) {
                            float v = acc[mt][nt][h * 2 + e];
                            if (bias) v += bias[col];
                            mx = fmaxf(mx, v);
                        }
                    }
                }
#pragma unroll
                for (int nt = 0; nt < 4; nt++) {
#pragma unroll
                    for (int e = 0; e < 2; e++) {
                        int col = n0 + wn * 32 + nt * 8 + tq * 2 + e;
                        if (col < N) {
                            float v = acc[mt][nt][h * 2 + e];
                            if (bias) v += bias[col];
                            sm += __expf(v - mx);
                            if (ok && col == lab) d_labv[m] = v;
                        }
                    }
                }
                // quad butterfly merge (lanes tq=0..3)
#pragma unroll
                for (int off = 1; off <= 2; off <<= 1) {
                    float om = __shfl_xor_sync(0xffffffff, mx, off);
                    float os = __shfl_xor_sync(0xffffffff, sm, off);
                    ol_merge(mx, sm, om, os);
                }
                if (tq == 0) spart[rloc][wn] = make_float2(mx, sm);
            }
        }
        __syncthreads();
        if (tid < 128) {
            float mx = -1e30f, sm = 0.f;
#pragma unroll
            for (int w = 0; w < 4; w++) {
                float2 p = spart[tid][w];
                ol_merge(mx, sm, p.x, p.y);
            }
            int m = m0 + tid;
            if (m < cnt)
                d_part[(size_t)m * PT_STRIDE + blockIdx.x] = make_float2(mx, sm);
        }
        return;
    }

    // ---- plain epilogue (stage-1 GEMMs) ----
#pragma unroll
    for (int mt = 0; mt < 4; mt++) {
        int r0 = m0 + wm * 64 + mt * 16 + gq;
        int r1 = r0 + 8;
#pragma unroll
        for (int nt = 0; nt < 4; nt++) {
            int cb = n0 + wn * 32 + nt * 8 + tq * 2;
            if (r0 < cnt) {
                if (cb < N)     C[(size_t)r0 * N + cb]     = acc[mt][nt][0];
                if (cb + 1 < N) C[(size_t)r0 * N + cb + 1] = acc[mt][nt][1];
            }
            if (r1 < cnt) {
                if (cb < N)     C[(size_t)r1 * N + cb]     = acc[mt][nt][2];
                if (cb + 1 < N) C[(size_t)r1 * N + cb + 1] = acc[mt][nt][3];
            }
        }
    }
}

// ---------------------------------------------------------------------------
// merge per-tile partials -> nll per token. one warp per compact row.
// first==1: d_nll[tok] = nll (head, covers all tokens); else +=.
// ---------------------------------------------------------------------------
__global__ __launch_bounds__(32)
void ce_merge(int ntiles, int idx_sel, int cnt_sel, int first) {
    int cnt = (cnt_sel == 0) ? N_TOK : ((cnt_sel == 1) ? d_cnt0 : d_cnt1);
    if (cnt > N_TOK) cnt = N_TOK;
    int b = blockIdx.x;
    if (b >= cnt) return;
    int lane = threadIdx.x;

    float mx = -1e30f, sm = 0.f;
    for (int t = lane; t < ntiles; t += 32) {
        float2 p = d_part[(size_t)b * PT_STRIDE + t];
        ol_merge(mx, sm, p.x, p.y);
    }
#pragma unroll
    for (int off = 16; off > 0; off >>= 1) {
        float om = __shfl_xor_sync(0xffffffff, mx, off);
        float os = __shfl_xor_sync(0xffffffff, sm, off);
        ol_merge(mx, sm, om, os);
    }
    if (lane == 0) {
        int tok = (idx_sel == 0) ? b : ((idx_sel == 1) ? d_idx0[b] : d_idx1[b]);
        tok = min(max(tok, 0), N_TOK - 1);
        float nll = logf(sm) + mx - d_labv[b];
        if (first) d_nll[tok] = nll;
        else       d_nll[tok] += nll;
    }
}

__global__ void reduce_kernel(float* __restrict__ out) {
    __shared__ float s[1024];
    float a = 0.0f;
    for (int i = threadIdx.x; i < N_TOK; i += 1024) a += d_nll[i];
    s[threadIdx.x] = a;
    __syncthreads();
#pragma unroll
    for (int k = 512; k > 0; k >>= 1) {
        if (threadIdx.x < k) s[threadIdx.x] += s[threadIdx.x + k];
        __syncthreads();
    }
    if (threadIdx.x == 0) out[0] = s[0] / (float)N_TOK;
}

// ---------------------------------------------------------------------------
extern "C" void kernel_launch(void* const* d_in, const int* in_sizes, int n_in,
                              void* d_out, int out_size) {
    const float* w_in   = (const float*)d_in[0];
    const int*   target = (const int*)d_in[1];
    const float* head_w = (const float*)d_in[2];
    const float* head_b = (const float*)d_in[3];
    const float* t0w1   = (const float*)d_in[4];
    const float* t0w2   = (const float*)d_in[5];
    const float* t1w1   = (const float*)d_in[6];
    const float* t1w2   = (const float*)d_in[7];
    float* out = (float*)d_out;

    init_kernel<<<1, 32>>>();
    gather_kernel<<<(N_TOK + 255) / 256, 256>>>(target);

    // ---- head: fused CE over w_in @ head_w.T + head_b ----
    {
        dim3 g((2002 + 127) / 128, N_TOK / 128);
        gemm_mma<<<g, 256>>>(w_in, head_w, head_b, 0, 0, 0, 0, 2002, 1024, 1);
        ce_merge<<<N_TOK, 32>>>((2002 + 127) / 128, 0, 0, /*first*/1);
    }
    // ---- tail0 (targets in [2000,10000)) ----
    {
        dim3 g1(1024 / 128, N_TOK / 128);
        gemm_mma<<<g1, 256>>>(w_in, t0w1, nullptr, 0, 1, 1, 1, 1024, 1024, 0);
        dim3 g2((8000 + 127) / 128, N_TOK / 128);
        gemm_mma<<<g2, 256>>>(nullptr, t0w2, nullptr, 1, 0, 0, 1, 8000, 1024, 1);
        ce_merge<<<N_TOK, 32>>>((8000 + 127) / 128, 1, 1, 0);
    }
    // ---- tail1 (targets in [10000,50000)) ----
    {
        dim3 g1(256 / 128, N_TOK / 128);
        gemm_mma<<<g1, 256>>>(w_in, t1w1, nullptr, 0, 2, 2, 2, 256, 1024, 0);
        dim3 g2((40000 + 127) / 128, N_TOK / 128);
        gemm_mma<<<g2, 256>>>(nullptr, t1w2, nullptr, 2, 0, 0, 2, 40000, 256, 1);
        ce_merge<<<N_TOK, 32>>>((40000 + 127) / 128, 2, 2, 0);
    }

    reduce_kernel<<<1, 1024>>>(out);
}

// round 8
// speedup vs baseline: 3.6662x; 1.0002x over previous
#include <cuda_runtime.h>
#include <cuda_fp16.h>
#include <cstdint>

// ---------------------------------------------------------------------------
// AdaptiveSoftmax — fp16 mma.sync, fp16 gmem operands, merged launches,
// fused-CE epilogue.
//   0: w_in [4096,1024] f32   1: target [4096] i32
//   2: head_w [2002,1024] f32 3: head_b [2002] f32
//   4: tail0_w1 [1024,1024]   5: tail0_w2 [8000,1024]
//   6: tail1_w1 [256,1024]    7: tail1_w2 [40000,256]
//   out: scalar f32 loss
// ---------------------------------------------------------------------------

#define N_TOK 4096
#define PT_STRIDE 320

// fp16 operand scratch (u32 = 2 packed halves)
__device__ __align__(16) uint32_t d_winh [2097152];   // 4096*1024/2
__device__ __align__(16) uint32_t d_hwh  [1025024];   // 2002*1024/2
__device__ __align__(16) uint32_t d_t0w1h[524288];    // 1024*1024/2
__device__ __align__(16) uint32_t d_t0w2h[4096000];   // 8000*1024/2
__device__ __align__(16) uint32_t d_t1w1h[131072];    // 256*1024/2
__device__ __align__(16) uint32_t d_t1w2h[5120000];   // 40000*256/2
__device__ __align__(16) uint32_t d_h0h  [2097152];   // 4096*1024/2
__device__ __align__(16) uint32_t d_h1h  [524288];    // 4096*256/2

__device__ __align__(16) float2 d_part[(size_t)3 * N_TOK * PT_STRIDE];
__device__ float d_labv[3 * N_TOK];
__device__ float d_nllv[3 * N_TOK];
__device__ int   d_labh[N_TOK];
__device__ int   d_lab0[N_TOK];
__device__ int   d_lab1[N_TOK];
__device__ int   d_idx0[N_TOK];
__device__ int   d_idx1[N_TOK];
__device__ int   d_cnt0;
__device__ int   d_cnt1;

// ---------------------------------------------------------------------------
__global__ void init_kernel() {
    if (threadIdx.x == 0) { d_cnt0 = 0; d_cnt1 = 0; }
}

__global__ void gather_kernel(const int* __restrict__ target) {
    int i = blockIdx.x * blockDim.x + threadIdx.x;
    if (i >= N_TOK) return;
    int t = target[i];
    int labh = t;
    if (t >= 2000 && t < 10000) {
        labh = 2000;
        int p = atomicAdd(&d_cnt0, 1);
        if (p < N_TOK) { d_idx0[p] = i; d_lab0[p] = t - 2000; }
    } else if (t >= 10000 && t < 50000) {
        labh = 2001;
        int p = atomicAdd(&d_cnt1, 1);
        if (p < N_TOK) { d_idx1[p] = i; d_lab1[p] = t - 10000; }
    }
    d_labh[i] = min(max(labh, 0), 2001);
}

// ---------------------------------------------------------------------------
__device__ __forceinline__ uint32_t pack_h2(float x, float y) {
    __half2 h = __floats2half2_rn(x, y);
    return *reinterpret_cast<uint32_t*>(&h);
}

// fused f32 -> packed f16 conversion of all 6 input tensors (8 elems/thread)
#define CS0 524288u    // w_in
#define CS1 256256u    // head_w
#define CS2 131072u    // t0w1
#define CS3 1024000u   // t0w2
#define CS4 32768u     // t1w1
#define CS5 1280000u   // t1w2
#define CTOT (CS0+CS1+CS2+CS3+CS4+CS5)

__global__ __launch_bounds__(256)
void convert_kernel(const float* __restrict__ w_in, const float* __restrict__ head_w,
                    const float* __restrict__ t0w1, const float* __restrict__ t0w2,
                    const float* __restrict__ t1w1, const float* __restrict__ t1w2) {
    size_t i = (size_t)blockIdx.x * 256 + threadIdx.x;
    if (i >= CTOT) return;
    const float* src; uint32_t* dst; size_t off = i;
    if (i < CS0)                       { src = w_in;   dst = d_winh; }
    else if ((off -= CS0) < CS1)       { src = head_w; dst = d_hwh; }
    else if ((off -= CS1) < CS2)       { src = t0w1;   dst = d_t0w1h; }
    else if ((off -= CS2) < CS3)       { src = t0w2;   dst = d_t0w2h; }
    else if ((off -= CS3) < CS4)       { src = t1w1;   dst = d_t1w1h; }
    else       { off -= CS4;             src = t1w2;   dst = d_t1w2h; }
    float4 x = reinterpret_cast<const float4*>(src)[off * 2];
    float4 y = reinterpret_cast<const float4*>(src)[off * 2 + 1];
    uint4 o;
    o.x = pack_h2(x.x, x.y); o.y = pack_h2(x.z, x.w);
    o.z = pack_h2(y.x, y.y); o.w = pack_h2(y.z, y.w);
    reinterpret_cast<uint4*>(dst)[off] = o;
}

// ---------------------------------------------------------------------------
__device__ __forceinline__ void mma_f16(float* d, const uint32_t* a,
                                        const uint32_t* b) {
    asm volatile(
        "mma.sync.aligned.m16n8k16.row.col.f32.f16.f16.f32 "
        "{%0,%1,%2,%3}, {%4,%5,%6,%7}, {%8,%9}, {%0,%1,%2,%3};"
        : "+f"(d[0]), "+f"(d[1]), "+f"(d[2]), "+f"(d[3])
        : "r"(a[0]), "r"(a[1]), "r"(a[2]), "r"(a[3]), "r"(b[0]), "r"(b[1]));
}

__device__ __forceinline__ int slot_of(int p) {
    int g = p >> 3, q = p & 7;
    return g * 8 + (q & 3) * 2 + (q >> 2);
}

__device__ __forceinline__ void ol_merge(float& mx, float& sm, float om, float os) {
    float nm = fmaxf(mx, om);
    sm = sm * __expf(mx - nm) + os * __expf(om - nm);
    mx = nm;
}

// ---------------------------------------------------------------------------
// Unified GEMM. Block tile 128x128x32, 512 thr (16 warps: 2m x 8n), warp tile
// 64x16, m16n8k16 fp16/f32. Double-buffered fp16 smem, 1 sync per k-tile.
// stage 0: z=0 head (fused CE ph0), z=1 t0s1 -> d_h0h, z=2 t1s1 -> d_h1h
// stage 1: z=0 t1s2 (fused CE ph2), z=1 t0s2 (fused CE ph1)
// ---------------------------------------------------------------------------
__global__ __launch_bounds__(512)
void gemm512(const float* __restrict__ bias, int stage) {
    int z = blockIdx.z;
    const uint32_t *A, *Bw;
    uint32_t* Cout = nullptr;
    const int* idxArr = nullptr;
    const int* labArr = nullptr;
    int N, K, cnt, xmax, ce = 0, phase = 0;
    bool useBias = false;
    if (stage == 0) {
        if (z == 0) { A = d_winh; Bw = d_hwh;   N = 2002; K = 1024; cnt = N_TOK;
                      xmax = 16; ce = 1; phase = 0; labArr = d_labh; useBias = true; }
        else if (z == 1) { A = d_winh; Bw = d_t0w1h; N = 1024; K = 1024; cnt = d_cnt0;
                      xmax = 8; idxArr = d_idx0; Cout = d_h0h; }
        else        { A = d_winh; Bw = d_t1w1h; N = 256;  K = 1024; cnt = d_cnt1;
                      xmax = 2; idxArr = d_idx1; Cout = d_h1h; }
    } else {
        if (z == 0) { A = d_h1h; Bw = d_t1w2h; N = 40000; K = 256;  cnt = d_cnt1;
                      xmax = 313; ce = 1; phase = 2; labArr = d_lab1; }
        else        { A = d_h0h; Bw = d_t0w2h; N = 8000;  K = 1024; cnt = d_cnt0;
                      xmax = 63;  ce = 1; phase = 1; labArr = d_lab0; }
    }
    if (cnt > N_TOK) cnt = N_TOK;
    if ((int)blockIdx.x >= xmax) return;
    int m0 = blockIdx.y * 128;
    int n0 = blockIdx.x * 128;
    if (m0 >= cnt) return;

    __shared__ __align__(16) uint32_t Ash[2][2048];
    __shared__ __align__(16) uint32_t Bsh[2][2048];
    __shared__ float2 spart[128][8];

    int tid  = threadIdx.x;
    int lane = tid & 31;
    int warp = tid >> 5;
    int wm = warp & 1;       // m offset wm*64
    int wn = warp >> 1;      // n offset wn*16

    // loader: 1 row per thread per matrix, uint4 chunk j (kpairs 4j..4j+3)
    int lrow = tid >> 2;
    int j    = tid & 3;
    int xmS  = 4 * (lrow & 3);
    int s0 = slot_of(4 * j)     ^ xmS;
    int s1 = slot_of(4 * j + 1) ^ xmS;
    int s2 = slot_of(4 * j + 2) ^ xmS;
    int s3 = slot_of(4 * j + 3) ^ xmS;
    int sBase = lrow * 16;

    int Ku = K >> 1;  // u32 per row
    int am = m0 + lrow;
    int arow = (am < cnt) ? (idxArr ? idxArr[am] : am) : 0;
    arow = min(max(arow, 0), N_TOK - 1);
    const uint32_t* aP = A + (size_t)arow * Ku + j * 4;
    int bn = n0 + lrow;
    const uint32_t* bP = Bw + (size_t)min(bn, N - 1) * Ku + j * 4;

    float acc[4][2][4];
#pragma unroll
    for (int mt = 0; mt < 4; mt++)
#pragma unroll
        for (int nt = 0; nt < 2; nt++)
#pragma unroll
            for (int e = 0; e < 4; e++) acc[mt][nt][e] = 0.0f;

    int gq = lane >> 2;
    int tq = lane & 3;
    int xmL = 4 * (gq & 3);

    // prime buffer 0
    uint4 aR = *reinterpret_cast<const uint4*>(aP);
    uint4 bR = *reinterpret_cast<const uint4*>(bP);
    Ash[0][sBase + s0] = aR.x; Ash[0][sBase + s1] = aR.y;
    Ash[0][sBase + s2] = aR.z; Ash[0][sBase + s3] = aR.w;
    Bsh[0][sBase + s0] = bR.x; Bsh[0][sBase + s1] = bR.y;
    Bsh[0][sBase + s2] = bR.z; Bsh[0][sBase + s3] = bR.w;
    __syncthreads();

    int nk = K >> 5;
    for (int kt = 0; kt < nk; kt++) {
        int cur = kt & 1, nxt = cur ^ 1;
        bool more = (kt + 1 < nk);
        if (more) {
            aR = *reinterpret_cast<const uint4*>(aP + (kt + 1) * 16);
            bR = *reinterpret_cast<const uint4*>(bP + (kt + 1) * 16);
        }
#pragma unroll
        for (int ks = 0; ks < 2; ks++) {
            int sIdx = (ks * 8 + 2 * tq) ^ xmL;
            uint32_t afr[4][4], bfr[2][2];
#pragma unroll
            for (int mt = 0; mt < 4; mt++) {
                int ra = wm * 64 + mt * 16 + gq;
                uint2 lo = *reinterpret_cast<const uint2*>(&Ash[cur][ra * 16 + sIdx]);
                uint2 hi = *reinterpret_cast<const uint2*>(&Ash[cur][(ra + 8) * 16 + sIdx]);
                afr[mt][0] = lo.x; afr[mt][1] = hi.x;
                afr[mt][2] = lo.y; afr[mt][3] = hi.y;
            }
#pragma unroll
            for (int nt = 0; nt < 2; nt++) {
                int rb = wn * 16 + nt * 8 + gq;
                uint2 bb = *reinterpret_cast<const uint2*>(&Bsh[cur][rb * 16 + sIdx]);
                bfr[nt][0] = bb.x; bfr[nt][1] = bb.y;
            }
#pragma unroll
            for (int mt = 0; mt < 4; mt++)
#pragma unroll
                for (int nt = 0; nt < 2; nt++)
                    mma_f16(acc[mt][nt], afr[mt], bfr[nt]);
        }
        if (more) {
            Ash[nxt][sBase + s0] = aR.x; Ash[nxt][sBase + s1] = aR.y;
            Ash[nxt][sBase + s2] = aR.z; Ash[nxt][sBase + s3] = aR.w;
            Bsh[nxt][sBase + s0] = bR.x; Bsh[nxt][sBase + s1] = bR.y;
            Bsh[nxt][sBase + s2] = bR.z; Bsh[nxt][sBase + s3] = bR.w;
        }
        __syncthreads();
    }

    if (ce) {
        // ---- fused CE epilogue ----
        float* labv = d_labv + phase * N_TOK;
#pragma unroll
        for (int mt = 0; mt < 4; mt++) {
#pragma unroll
            for (int h = 0; h < 2; h++) {
                int rloc = wm * 64 + mt * 16 + gq + h * 8;
                int m = m0 + rloc;
                bool ok = (m < cnt);
                int lab = ok ? labArr[m] : -1;
                float mx = -1e30f, sm = 0.f;
#pragma unroll
                for (int nt = 0; nt < 2; nt++) {
#pragma unroll
                    for (int e = 0; e < 2; e++) {
                        int col = n0 + wn * 16 + nt * 8 + tq * 2 + e;
                        if (col < N) {
                            float v = acc[mt][nt][h * 2 + e];
                            if (useBias) v += bias[col];
                            mx = fmaxf(mx, v);
                        }
                    }
                }
#pragma unroll
                for (int nt = 0; nt < 2; nt++) {
#pragma unroll
                    for (int e = 0; e < 2; e++) {
                        int col = n0 + wn * 16 + nt * 8 + tq * 2 + e;
                        if (col < N) {
                            float v = acc[mt][nt][h * 2 + e];
                            if (useBias) v += bias[col];
                            sm += __expf(v - mx);
                            if (ok && col == lab) labv[m] = v;
                        }
                    }
                }
#pragma unroll
                for (int off = 1; off <= 2; off <<= 1) {
                    float om = __shfl_xor_sync(0xffffffff, mx, off);
                    float os = __shfl_xor_sync(0xffffffff, sm, off);
                    ol_merge(mx, sm, om, os);
                }
                if (tq == 0) spart[rloc][wn] = make_float2(mx, sm);
            }
        }
        __syncthreads();
        if (tid < 128) {
            float mx = -1e30f, sm = 0.f;
#pragma unroll
            for (int w = 0; w < 8; w++) {
                float2 p = spart[tid][w];
                ol_merge(mx, sm, p.x, p.y);
            }
            int m = m0 + tid;
            if (m < cnt)
                d_part[((size_t)phase * N_TOK + m) * PT_STRIDE + blockIdx.x] =
                    make_float2(mx, sm);
        }
        return;
    }

    // ---- plain epilogue: write packed fp16 hidden ----
    int Nu = N >> 1;
#pragma unroll
    for (int mt = 0; mt < 4; mt++) {
#pragma unroll
        for (int h = 0; h < 2; h++) {
            int r = m0 + wm * 64 + mt * 16 + gq + h * 8;
            if (r >= cnt) continue;
#pragma unroll
            for (int nt = 0; nt < 2; nt++) {
                int cb = n0 + wn * 16 + nt * 8 + tq * 2;
                if (cb < N)
                    Cout[(size_t)r * Nu + (cb >> 1)] =
                        pack_h2(acc[mt][nt][h * 2 + 0], acc[mt][nt][h * 2 + 1]);
            }
        }
    }
}

// ---------------------------------------------------------------------------
// merge partials -> per-phase nll. grid (N_TOK, 3). one warp per row.
// ---------------------------------------------------------------------------
__global__ __launch_bounds__(32)
void ce_merge() {
    int phase = blockIdx.y;
    int ntiles = (phase == 0) ? 16 : ((phase == 1) ? 63 : 313);
    int cnt    = (phase == 0) ? N_TOK : ((phase == 1) ? d_cnt0 : d_cnt1);
    if (cnt > N_TOK) cnt = N_TOK;
    int b = blockIdx.x;
    if (b >= cnt) return;
    int lane = threadIdx.x;

    const float2* base = d_part + ((size_t)phase * N_TOK + b) * PT_STRIDE;
    float mx = -1e30f, sm = 0.f;
    for (int t = lane; t < ntiles; t += 32) {
        float2 p = base[t];
        ol_merge(mx, sm, p.x, p.y);
    }
#pragma unroll
    for (int off = 16; off > 0; off >>= 1) {
        float om = __shfl_xor_sync(0xffffffff, mx, off);
        float os = __shfl_xor_sync(0xffffffff, sm, off);
        ol_merge(mx, sm, om, os);
    }
    if (lane == 0)
        d_nllv[phase * N_TOK + b] = logf(sm) + mx - d_labv[phase * N_TOK + b];
}

__global__ __launch_bounds__(1024)
void reduce_kernel(float* __restrict__ out) {
    __shared__ double s[1024];
    int c0 = min(d_cnt0, N_TOK), c1 = min(d_cnt1, N_TOK);
    double a = 0.0;
    for (int i = threadIdx.x; i < N_TOK; i += 1024) a += (double)d_nllv[i];
    for (int i = threadIdx.x; i < c0;    i += 1024) a += (double)d_nllv[N_TOK + i];
    for (int i = threadIdx.x; i < c1;    i += 1024) a += (double)d_nllv[2 * N_TOK + i];
    s[threadIdx.x] = a;
    __syncthreads();
#pragma unroll
    for (int k = 512; k > 0; k >>= 1) {
        if (threadIdx.x < k) s[threadIdx.x] += s[threadIdx.x + k];
        __syncthreads();
    }
    if (threadIdx.x == 0) out[0] = (float)(s[0] / (double)N_TOK);
}

// ---------------------------------------------------------------------------
extern "C" void kernel_launch(void* const* d_in, const int* in_sizes, int n_in,
                              void* d_out, int out_size) {
    const float* w_in   = (const float*)d_in[0];
    const int*   target = (const int*)d_in[1];
    const float* head_w = (const float*)d_in[2];
    const float* head_b = (const float*)d_in[3];
    const float* t0w1   = (const float*)d_in[4];
    const float* t0w2   = (const float*)d_in[5];
    const float* t1w1   = (const float*)d_in[6];
    const float* t1w2   = (const float*)d_in[7];
    float* out = (float*)d_out;

    init_kernel<<<1, 32>>>();
    gather_kernel<<<(N_TOK + 255) / 256, 256>>>(target);
    convert_kernel<<<(CTOT + 255) / 256, 256>>>(w_in, head_w, t0w1, t0w2,
                                                t1w1, t1w2);

    // stage A: head (fused CE) + t0s1 + t1s1
    gemm512<<<dim3(16, 32, 3), 512>>>(head_b, 0);
    // stage B: t1s2 + t0s2 (fused CE)
    gemm512<<<dim3(313, 32, 2), 512>>>(head_b, 1);

    ce_merge<<<dim3(N_TOK, 3), 32>>>();
    reduce_kernel<<<1, 1024>>>(out);
}

// round 9
// speedup vs baseline: 5.9265x; 1.6165x over previous
#include <cuda_runtime.h>
#include <cuda_fp16.h>
#include <cstdint>

// ---------------------------------------------------------------------------
// AdaptiveSoftmax — fp16 mma.sync, cp.async double-buffered pipeline,
// pre-tiled fp16 operands, fused-CE epilogue, merged launches.
//   0: w_in [4096,1024] f32   1: target [4096] i32
//   2: head_w [2002,1024] f32 3: head_b [2002] f32
//   4: tail0_w1 [1024,1024]   5: tail0_w2 [8000,1024]
//   6: tail1_w1 [256,1024]    7: tail1_w2 [40000,256]
//   out: scalar f32 loss
// ---------------------------------------------------------------------------

#define N_TOK 4096
#define PT_STRIDE 320

// fp16 operands in tiled layout: u32 idx = ((kt*R + row)*16 + slot)
// slot(p) = (p&3)*4 + (p>>2) for kpair p in k-tile of 32 halves.
__device__ __align__(16) uint32_t d_winh [2097152];   // 4096*1024/2
__device__ __align__(16) uint32_t d_hwh  [1025024];   // 2002*1024/2
__device__ __align__(16) uint32_t d_t0w1h[524288];
__device__ __align__(16) uint32_t d_t0w2h[4096000];
__device__ __align__(16) uint32_t d_t1w1h[131072];
__device__ __align__(16) uint32_t d_t1w2h[5120000];
__device__ __align__(16) uint32_t d_h0h  [2097152];   // R=4096, K=1024
__device__ __align__(16) uint32_t d_h1h  [524288];    // R=4096, K=256

__device__ __align__(16) float2 d_part[(size_t)3 * N_TOK * PT_STRIDE];
__device__ float d_labv[3 * N_TOK];
__device__ float d_nllv[3 * N_TOK];
__device__ int   d_labh[N_TOK];
__device__ int   d_lab0[N_TOK];
__device__ int   d_lab1[N_TOK];
__device__ int   d_idx0[N_TOK];
__device__ int   d_idx1[N_TOK];
__device__ int   d_cnt0;
__device__ int   d_cnt1;

// ---------------------------------------------------------------------------
__global__ void init_kernel() {
    if (threadIdx.x == 0) { d_cnt0 = 0; d_cnt1 = 0; }
}

__global__ void gather_kernel(const int* __restrict__ target) {
    int i = blockIdx.x * blockDim.x + threadIdx.x;
    if (i >= N_TOK) return;
    int t = target[i];
    int labh = t;
    if (t >= 2000 && t < 10000) {
        labh = 2000;
        int p = atomicAdd(&d_cnt0, 1);
        if (p < N_TOK) { d_idx0[p] = i; d_lab0[p] = t - 2000; }
    } else if (t >= 10000 && t < 50000) {
        labh = 2001;
        int p = atomicAdd(&d_cnt1, 1);
        if (p < N_TOK) { d_idx1[p] = i; d_lab1[p] = t - 10000; }
    }
    d_labh[i] = min(max(labh, 0), 2001);
}

// ---------------------------------------------------------------------------
__device__ __forceinline__ uint32_t pack_h2(float x, float y) {
    __half2 h = __floats2half2_rn(x, y);
    return *reinterpret_cast<uint32_t*>(&h);
}

// f32 -> tiled fp16. one thread per uint4 chunk (= 8 halves).
#define W0 524288
#define W1 256256
#define W2 131072
#define W3 1024000
#define W4 32768
#define W5 1280000
#define WTOT (W0+W1+W2+W3+W4+W5)

__global__ __launch_bounds__(256)
void convert_kernel(const float* __restrict__ w_in, const float* __restrict__ head_w,
                    const float* __restrict__ t0w1, const float* __restrict__ t0w2,
                    const float* __restrict__ t1w1, const float* __restrict__ t1w2) {
    int i = blockIdx.x * 256 + threadIdx.x;
    if (i >= WTOT) return;
    const float* src; uint32_t* dst; int R, K, c = i;
    if (c < W0)              { src = w_in;   dst = d_winh;  R = 4096;  K = 1024; }
    else if ((c -= W0) < W1) { src = head_w; dst = d_hwh;   R = 2002;  K = 1024; }
    else if ((c -= W1) < W2) { src = t0w1;   dst = d_t0w1h; R = 1024;  K = 1024; }
    else if ((c -= W2) < W3) { src = t0w2;   dst = d_t0w2h; R = 8000;  K = 1024; }
    else if ((c -= W3) < W4) { src = t1w1;   dst = d_t1w1h; R = 256;   K = 1024; }
    else      { c -= W4;       src = t1w2;   dst = d_t1w2h; R = 40000; K = 256;  }
    int nrow4 = R * 4;
    int kt = c / nrow4;
    int rem = c - kt * nrow4;
    int r = rem >> 2, g = rem & 3;
    const float* s = src + (size_t)r * K + kt * 32 + 2 * g;
    uint4 o;
    o.x = pack_h2(s[0],  s[1]);    // kpair g       (ks0 lo)
    o.y = pack_h2(s[8],  s[9]);    // kpair 4+g     (ks0 hi)
    o.z = pack_h2(s[16], s[17]);   // kpair 8+g     (ks1 lo)
    o.w = pack_h2(s[24], s[25]);   // kpair 12+g    (ks1 hi)
    reinterpret_cast<uint4*>(dst)[((size_t)kt * R + r) * 4 + g] = o;
}

// ---------------------------------------------------------------------------
__device__ __forceinline__ void mma_f16(float* d, uint32_t a0, uint32_t a1,
                                        uint32_t a2, uint32_t a3,
                                        uint32_t b0, uint32_t b1) {
    asm volatile(
        "mma.sync.aligned.m16n8k16.row.col.f32.f16.f16.f32 "
        "{%0,%1,%2,%3}, {%4,%5,%6,%7}, {%8,%9}, {%0,%1,%2,%3};"
        : "+f"(d[0]), "+f"(d[1]), "+f"(d[2]), "+f"(d[3])
        : "r"(a0), "r"(a1), "r"(a2), "r"(a3), "r"(b0), "r"(b1));
}

__device__ __forceinline__ void cp16(uint32_t saddr, const void* g) {
    asm volatile("cp.async.cg.shared.global [%0], [%1], 16;"
                 :: "r"(saddr), "l"(g));
}
__device__ __forceinline__ void cp_commit() {
    asm volatile("cp.async.commit_group;" ::: "memory");
}
__device__ __forceinline__ void cp_wait0() {
    asm volatile("cp.async.wait_group 0;" ::: "memory");
}

__device__ __forceinline__ void ol_merge(float& mx, float& sm, float om, float os) {
    float nm = fmaxf(mx, om);
    sm = sm * __expf(mx - nm) + os * __expf(om - nm);
    mx = nm;
}

// ---------------------------------------------------------------------------
// Unified GEMM: block 128x128x32, 256 thr, 8 warps (2m x 4n), warp 64x32.
// cp.async double buffer, 1 sync/k-tile, LDS.128 fragment loads.
// ---------------------------------------------------------------------------
__global__ __launch_bounds__(256, 2)
void gemm256(const float* __restrict__ bias, int stage) {
    int z = blockIdx.z;
    const uint32_t *A, *Bw;
    uint32_t* Cout = nullptr;
    const int* idxArr = nullptr;
    const int* labArr = nullptr;
    int N, K, cnt, xmax, ce = 0, phase = 0;
    bool useBias = false;
    if (stage == 0) {
        if (z == 0)      { A = d_winh; Bw = d_hwh;   N = 2002; K = 1024; cnt = N_TOK;
                           xmax = 16; ce = 1; phase = 0; labArr = d_labh; useBias = true; }
        else if (z == 1) { A = d_winh; Bw = d_t0w1h; N = 1024; K = 1024; cnt = d_cnt0;
                           xmax = 8; idxArr = d_idx0; Cout = d_h0h; }
        else             { A = d_winh; Bw = d_t1w1h; N = 256;  K = 1024; cnt = d_cnt1;
                           xmax = 2; idxArr = d_idx1; Cout = d_h1h; }
    } else {
        if (z == 0)      { A = d_h1h; Bw = d_t1w2h; N = 40000; K = 256;  cnt = d_cnt1;
                           xmax = 313; ce = 1; phase = 2; labArr = d_lab1; }
        else             { A = d_h0h; Bw = d_t0w2h; N = 8000;  K = 1024; cnt = d_cnt0;
                           xmax = 63;  ce = 1; phase = 1; labArr = d_lab0; }
    }
    if ((int)blockIdx.x >= xmax) return;
    if (cnt > N_TOK) cnt = N_TOK;
    int m0 = blockIdx.y * 128;
    int n0 = blockIdx.x * 128;
    if (m0 >= cnt) return;

    __shared__ __align__(16) uint32_t Ash[2][2048];
    __shared__ __align__(16) uint32_t Bsh[2][2048];
    __shared__ float2 spart[128][4];

    int tid  = threadIdx.x;
    int lane = tid & 31;
    int warp = tid >> 5;
    int wm = warp & 1;       // m offset wm*64
    int wn = warp >> 1;      // n offset wn*32

    // ---- loader mapping: row = tid>>1, groups {2h, 2h+1} ----
    int lrow = tid >> 1;
    int hh   = tid & 1;
    int g0 = 2 * hh, g1 = 2 * hh + 1;
    int swz = (lrow >> 1) & 3;
    uint32_t aSh = (uint32_t)__cvta_generic_to_shared(&Ash[0][0]);
    uint32_t bSh = (uint32_t)__cvta_generic_to_shared(&Bsh[0][0]);
    uint32_t dA0 = (lrow * 16 + 4 * (g0 ^ swz)) << 2;
    uint32_t dA1 = (lrow * 16 + 4 * (g1 ^ swz)) << 2;

    int am = m0 + lrow;
    int arow = (am < cnt) ? (idxArr ? idxArr[am] : am) : 0;
    arow = min(max(arow, 0), N_TOK - 1);
    int brow = min(n0 + lrow, N - 1);

    float acc[4][4][4];
#pragma unroll
    for (int mt = 0; mt < 4; mt++)
#pragma unroll
        for (int nt = 0; nt < 4; nt++)
#pragma unroll
            for (int e = 0; e < 4; e++) acc[mt][nt][e] = 0.0f;

    int gq = lane >> 2;
    int tq = lane & 3;

    // prime buffer 0
    {
        const uint32_t* ag = A  + ((size_t)0 * 4096 + arow) * 16;
        const uint32_t* bg = Bw + ((size_t)0 * N + brow) * 16;
        cp16(aSh + dA0, ag + 4 * g0);
        cp16(aSh + dA1, ag + 4 * g1);
        cp16(bSh + dA0, bg + 4 * g0);
        cp16(bSh + dA1, bg + 4 * g1);
        cp_commit();
    }

    int nk = K >> 5;
    for (int kt = 0; kt < nk; kt++) {
        int buf = kt & 1;
        cp_wait0();
        __syncthreads();
        if (kt + 1 < nk) {
            int nb = buf ^ 1;
            const uint32_t* ag = A  + ((size_t)(kt + 1) * 4096 + arow) * 16;
            const uint32_t* bg = Bw + ((size_t)(kt + 1) * N + brow) * 16;
            uint32_t boff = (uint32_t)nb * 8192;
            cp16(aSh + boff + dA0, ag + 4 * g0);
            cp16(aSh + boff + dA1, ag + 4 * g1);
            cp16(bSh + boff + dA0, bg + 4 * g0);
            cp16(bSh + boff + dA1, bg + 4 * g1);
            cp_commit();
        }

        // ---- compute (both k16 steps from one uint4 per row) ----
        uint4 bf[4];
#pragma unroll
        for (int nt = 0; nt < 4; nt++) {
            int rb = wn * 32 + nt * 8 + gq;
            int gg = tq ^ ((rb >> 1) & 3);
            bf[nt] = *reinterpret_cast<const uint4*>(&Bsh[buf][rb * 16 + 4 * gg]);
        }
#pragma unroll
        for (int mt = 0; mt < 4; mt++) {
            int ra = wm * 64 + mt * 16 + gq;
            int gla = tq ^ ((ra >> 1) & 3);
            int glb = tq ^ (((ra + 8) >> 1) & 3);
            uint4 lo = *reinterpret_cast<const uint4*>(&Ash[buf][ra * 16 + 4 * gla]);
            uint4 hi = *reinterpret_cast<const uint4*>(&Ash[buf][(ra + 8) * 16 + 4 * glb]);
#pragma unroll
            for (int nt = 0; nt < 4; nt++)
                mma_f16(acc[mt][nt], lo.x, hi.x, lo.y, hi.y, bf[nt].x, bf[nt].y);
#pragma unroll
            for (int nt = 0; nt < 4; nt++)
                mma_f16(acc[mt][nt], lo.z, hi.z, lo.w, hi.w, bf[nt].z, bf[nt].w);
        }
        __syncthreads();
    }

    if (ce) {
        // ---- fused CE epilogue ----
        float* labv = d_labv + phase * N_TOK;
#pragma unroll
        for (int mt = 0; mt < 4; mt++) {
#pragma unroll
            for (int h = 0; h < 2; h++) {
                int rloc = wm * 64 + mt * 16 + gq + h * 8;
                int m = m0 + rloc;
                bool ok = (m < cnt);
                int lab = ok ? labArr[m] : -1;
                float mx = -1e30f, sm = 0.f;
#pragma unroll
                for (int nt = 0; nt < 4; nt++) {
#pragma unroll
                    for (int e = 0; e < 2; e++) {
                        int col = n0 + wn * 32 + nt * 8 + tq * 2 + e;
                        if (col < N) {
                            float v = acc[mt][nt][h * 2 + e];
                            if (useBias) v += bias[col];
                            mx = fmaxf(mx, v);
                        }
                    }
                }
#pragma unroll
                for (int nt = 0; nt < 4; nt++) {
#pragma unroll
                    for (int e = 0; e < 2; e++) {
                        int col = n0 + wn * 32 + nt * 8 + tq * 2 + e;
                        if (col < N) {
                            float v = acc[mt][nt][h * 2 + e];
                            if (useBias) v += bias[col];
                            sm += __expf(v - mx);
                            if (ok && col == lab) labv[m] = v;
                        }
                    }
                }
#pragma unroll
                for (int off = 1; off <= 2; off <<= 1) {
                    float om = __shfl_xor_sync(0xffffffff, mx, off);
                    float os = __shfl_xor_sync(0xffffffff, sm, off);
                    ol_merge(mx, sm, om, os);
                }
                if (tq == 0) spart[rloc][wn] = make_float2(mx, sm);
            }
        }
        __syncthreads();
        if (tid < 128) {
            float mx = -1e30f, sm = 0.f;
#pragma unroll
            for (int w = 0; w < 4; w++) {
                float2 p = spart[tid][w];
                ol_merge(mx, sm, p.x, p.y);
            }
            int m = m0 + tid;
            if (m < cnt)
                d_part[((size_t)phase * N_TOK + m) * PT_STRIDE + blockIdx.x] =
                    make_float2(mx, sm);
        }
        return;
    }

    // ---- plain epilogue: write h in tiled fp16 layout ----
#pragma unroll
    for (int mt = 0; mt < 4; mt++) {
#pragma unroll
        for (int h = 0; h < 2; h++) {
            int r = m0 + wm * 64 + mt * 16 + gq + h * 8;
            if (r >= cnt) continue;
#pragma unroll
            for (int nt = 0; nt < 4; nt++) {
                int cb = n0 + wn * 32 + nt * 8 + tq * 2;
                int kt = cb >> 5;
                int p  = (cb & 31) >> 1;
                int s  = (p & 3) * 4 + (p >> 2);
                Cout[((size_t)kt * 4096 + r) * 16 + s] =
                    pack_h2(acc[mt][nt][h * 2 + 0], acc[mt][nt][h * 2 + 1]);
            }
        }
    }
}

// ---------------------------------------------------------------------------
__global__ __launch_bounds__(32)
void ce_merge() {
    int phase = blockIdx.y;
    int ntiles = (phase == 0) ? 16 : ((phase == 1) ? 63 : 313);
    int cnt    = (phase == 0) ? N_TOK : ((phase == 1) ? d_cnt0 : d_cnt1);
    if (cnt > N_TOK) cnt = N_TOK;
    int b = blockIdx.x;
    if (b >= cnt) return;
    int lane = threadIdx.x;

    const float2* base = d_part + ((size_t)phase * N_TOK + b) * PT_STRIDE;
    float mx = -1e30f, sm = 0.f;
    for (int t = lane; t < ntiles; t += 32) {
        float2 p = base[t];
        ol_merge(mx, sm, p.x, p.y);
    }
#pragma unroll
    for (int off = 16; off > 0; off >>= 1) {
        float om = __shfl_xor_sync(0xffffffff, mx, off);
        float os = __shfl_xor_sync(0xffffffff, sm, off);
        ol_merge(mx, sm, om, os);
    }
    if (lane == 0)
        d_nllv[phase * N_TOK + b] = logf(sm) + mx - d_labv[phase * N_TOK + b];
}

__global__ __launch_bounds__(1024)
void reduce_kernel(float* __restrict__ out) {
    __shared__ double s[1024];
    int c0 = min(d_cnt0, N_TOK), c1 = min(d_cnt1, N_TOK);
    double a = 0.0;
    for (int i = threadIdx.x; i < N_TOK; i += 1024) a += (double)d_nllv[i];
    for (int i = threadIdx.x; i < c0;    i += 1024) a += (double)d_nllv[N_TOK + i];
    for (int i = threadIdx.x; i < c1;    i += 1024) a += (double)d_nllv[2 * N_TOK + i];
    s[threadIdx.x] = a;
    __syncthreads();
#pragma unroll
    for (int k = 512; k > 0; k >>= 1) {
        if (threadIdx.x < k) s[threadIdx.x] += s[threadIdx.x + k];
        __syncthreads();
    }
    if (threadIdx.x == 0) out[0] = (float)(s[0] / (double)N_TOK);
}

// ---------------------------------------------------------------------------
extern "C" void kernel_launch(void* const* d_in, const int* in_sizes, int n_in,
                              void* d_out, int out_size) {
    const float* w_in   = (const float*)d_in[0];
    const int*   target = (const int*)d_in[1];
    const float* head_w = (const float*)d_in[2];
    const float* head_b = (const float*)d_in[3];
    const float* t0w1   = (const float*)d_in[4];
    const float* t0w2   = (const float*)d_in[5];
    const float* t1w1   = (const float*)d_in[6];
    const float* t1w2   = (const float*)d_in[7];
    float* out = (float*)d_out;

    init_kernel<<<1, 32>>>();
    gather_kernel<<<(N_TOK + 255) / 256, 256>>>(target);
    convert_kernel<<<(WTOT + 255) / 256, 256>>>(w_in, head_w, t0w1, t0w2,
                                                t1w1, t1w2);

    // stage A: head (fused CE) + t0s1 + t1s1
    gemm256<<<dim3(16, 32, 3), 256>>>(head_b, 0);
    // stage B: t1s2 (fused CE) + t0s2 (fused CE)
    gemm256<<<dim3(313, 32, 2), 256>>>(head_b, 1);

    ce_merge<<<dim3(N_TOK, 3), 32>>>();
    reduce_kernel<<<1, 1024>>>(out);
}

// round 10
// speedup vs baseline: 6.1571x; 1.0389x over previous
#include <cuda_runtime.h>
#include <cuda_fp16.h>
#include <cstdint>

// ---------------------------------------------------------------------------
// AdaptiveSoftmax — fp16 mma.sync, 3-stage cp.async ring (1 sync/k-tile),
// pre-tiled fp16 operands, fused-CE epilogue, merged launches.
//   0: w_in [4096,1024] f32   1: target [4096] i32
//   2: head_w [2002,1024] f32 3: head_b [2002] f32
//   4: tail0_w1 [1024,1024]   5: tail0_w2 [8000,1024]
//   6: tail1_w1 [256,1024]    7: tail1_w2 [40000,256]
//   out: scalar f32 loss
// ---------------------------------------------------------------------------

#define N_TOK 4096
#define PT_STRIDE 320

// fp16 operands in tiled layout: u32 idx = ((kt*R + row)*16 + slot)
// slot(p) = (p&3)*4 + (p>>2) for kpair p in k-tile of 32 halves.
__device__ __align__(16) uint32_t d_winh [2097152];
__device__ __align__(16) uint32_t d_hwh  [1025024];
__device__ __align__(16) uint32_t d_t0w1h[524288];
__device__ __align__(16) uint32_t d_t0w2h[4096000];
__device__ __align__(16) uint32_t d_t1w1h[131072];
__device__ __align__(16) uint32_t d_t1w2h[5120000];
__device__ __align__(16) uint32_t d_h0h  [2097152];   // R=4096, K=1024
__device__ __align__(16) uint32_t d_h1h  [524288];    // R=4096, K=256

__device__ __align__(16) float2 d_part[(size_t)3 * N_TOK * PT_STRIDE];
__device__ float d_labv[3 * N_TOK];
__device__ float d_nllv[3 * N_TOK];
__device__ int   d_labh[N_TOK];
__device__ int   d_lab0[N_TOK];
__device__ int   d_lab1[N_TOK];
__device__ int   d_idx0[N_TOK];
__device__ int   d_idx1[N_TOK];
__device__ int   d_cnt0;
__device__ int   d_cnt1;

// ---------------------------------------------------------------------------
__global__ void init_kernel() {
    if (threadIdx.x == 0) { d_cnt0 = 0; d_cnt1 = 0; }
}

__global__ void gather_kernel(const int* __restrict__ target) {
    int i = blockIdx.x * blockDim.x + threadIdx.x;
    if (i >= N_TOK) return;
    int t = target[i];
    int labh = t;
    if (t >= 2000 && t < 10000) {
        labh = 2000;
        int p = atomicAdd(&d_cnt0, 1);
        if (p < N_TOK) { d_idx0[p] = i; d_lab0[p] = t - 2000; }
    } else if (t >= 10000 && t < 50000) {
        labh = 2001;
        int p = atomicAdd(&d_cnt1, 1);
        if (p < N_TOK) { d_idx1[p] = i; d_lab1[p] = t - 10000; }
    }
    d_labh[i] = min(max(labh, 0), 2001);
}

// ---------------------------------------------------------------------------
__device__ __forceinline__ uint32_t pack_h2(float x, float y) {
    __half2 h = __floats2half2_rn(x, y);
    return *reinterpret_cast<uint32_t*>(&h);
}

#define W0 524288
#define W1 256256
#define W2 131072
#define W3 1024000
#define W4 32768
#define W5 1280000
#define WTOT (W0+W1+W2+W3+W4+W5)

__global__ __launch_bounds__(256)
void convert_kernel(const float* __restrict__ w_in, const float* __restrict__ head_w,
                    const float* __restrict__ t0w1, const float* __restrict__ t0w2,
                    const float* __restrict__ t1w1, const float* __restrict__ t1w2) {
    int i = blockIdx.x * 256 + threadIdx.x;
    if (i >= WTOT) return;
    const float* src; uint32_t* dst; int R, K, c = i;
    if (c < W0)              { src = w_in;   dst = d_winh;  R = 4096;  K = 1024; }
    else if ((c -= W0) < W1) { src = head_w; dst = d_hwh;   R = 2002;  K = 1024; }
    else if ((c -= W1) < W2) { src = t0w1;   dst = d_t0w1h; R = 1024;  K = 1024; }
    else if ((c -= W2) < W3) { src = t0w2;   dst = d_t0w2h; R = 8000;  K = 1024; }
    else if ((c -= W3) < W4) { src = t1w1;   dst = d_t1w1h; R = 256;   K = 1024; }
    else      { c -= W4;       src = t1w2;   dst = d_t1w2h; R = 40000; K = 256;  }
    int nrow4 = R * 4;
    int kt = c / nrow4;
    int rem = c - kt * nrow4;
    int r = rem >> 2, g = rem & 3;
    const float* s = src + (size_t)r * K + kt * 32 + 2 * g;
    uint4 o;
    o.x = pack_h2(s[0],  s[1]);
    o.y = pack_h2(s[8],  s[9]);
    o.z = pack_h2(s[16], s[17]);
    o.w = pack_h2(s[24], s[25]);
    reinterpret_cast<uint4*>(dst)[((size_t)kt * R + r) * 4 + g] = o;
}

// ---------------------------------------------------------------------------
__device__ __forceinline__ void mma_f16(float* d, uint32_t a0, uint32_t a1,
                                        uint32_t a2, uint32_t a3,
                                        uint32_t b0, uint32_t b1) {
    asm volatile(
        "mma.sync.aligned.m16n8k16.row.col.f32.f16.f16.f32 "
        "{%0,%1,%2,%3}, {%4,%5,%6,%7}, {%8,%9}, {%0,%1,%2,%3};"
        : "+f"(d[0]), "+f"(d[1]), "+f"(d[2]), "+f"(d[3])
        : "r"(a0), "r"(a1), "r"(a2), "r"(a3), "r"(b0), "r"(b1));
}

__device__ __forceinline__ void cp16(uint32_t saddr, const void* g) {
    asm volatile("cp.async.cg.shared.global [%0], [%1], 16;"
                 :: "r"(saddr), "l"(g));
}
__device__ __forceinline__ void cp_commit() {
    asm volatile("cp.async.commit_group;" ::: "memory");
}
__device__ __forceinline__ void cp_wait1() {
    asm volatile("cp.async.wait_group 1;" ::: "memory");
}

__device__ __forceinline__ void ol_merge(float& mx, float& sm, float om, float os) {
    float nm = fmaxf(mx, om);
    sm = sm * __expf(mx - nm) + os * __expf(om - nm);
    mx = nm;
}

// ---------------------------------------------------------------------------
// Unified GEMM: block 128x128x32, 256 thr, 8 warps (2m x 4n), warp 64x32.
// 3-stage cp.async ring, ONE __syncthreads per k-tile.
// NOTE: CE spart buffer aliases pipeline slot 0 — valid because nk is 32 or 8
// in every phase, so the final tile lives in slot 1 and all slot-0 reads are
// ordered before the epilogue by the last-iteration barrier.
// ---------------------------------------------------------------------------
__global__ __launch_bounds__(256, 2)
void gemm256(const float* __restrict__ bias, int stage) {
    int z = blockIdx.z;
    const uint32_t *A, *Bw;
    uint32_t* Cout = nullptr;
    const int* idxArr = nullptr;
    const int* labArr = nullptr;
    int N, K, cnt, xmax, ce = 0, phase = 0;
    bool useBias = false;
    if (stage == 0) {
        if (z == 0)      { A = d_winh; Bw = d_hwh;   N = 2002; K = 1024; cnt = N_TOK;
                           xmax = 16; ce = 1; phase = 0; labArr = d_labh; useBias = true; }
        else if (z == 1) { A = d_winh; Bw = d_t0w1h; N = 1024; K = 1024; cnt = d_cnt0;
                           xmax = 8; idxArr = d_idx0; Cout = d_h0h; }
        else             { A = d_winh; Bw = d_t1w1h; N = 256;  K = 1024; cnt = d_cnt1;
                           xmax = 2; idxArr = d_idx1; Cout = d_h1h; }
    } else {
        if (z == 0)      { A = d_h1h; Bw = d_t1w2h; N = 40000; K = 256;  cnt = d_cnt1;
                           xmax = 313; ce = 1; phase = 2; labArr = d_lab1; }
        else             { A = d_h0h; Bw = d_t0w2h; N = 8000;  K = 1024; cnt = d_cnt0;
                           xmax = 63;  ce = 1; phase = 1; labArr = d_lab0; }
    }
    if ((int)blockIdx.x >= xmax) return;
    if (cnt > N_TOK) cnt = N_TOK;
    int m0 = blockIdx.y * 128;
    int n0 = blockIdx.x * 128;
    if (m0 >= cnt) return;

    // 3-slot ring: A slots at [s*2048], B slots at [6144 + s*2048] (u32 units)
    __shared__ __align__(16) uint32_t Smem[12288];   // 48KB exactly
    uint32_t* Ab = Smem;
    uint32_t* Bb = Smem + 6144;
    float2 (*spart)[4] = reinterpret_cast<float2(*)[4]>(Smem);  // aliases slot 0

    int tid  = threadIdx.x;
    int lane = tid & 31;
    int warp = tid >> 5;
    int wm = warp & 1;
    int wn = warp >> 1;

    int lrow = tid >> 1;
    int hh   = tid & 1;
    int g0 = 2 * hh, g1 = 2 * hh + 1;
    int swz = (lrow >> 1) & 3;
    uint32_t aShBase = (uint32_t)__cvta_generic_to_shared(Ab);
    uint32_t bShBase = (uint32_t)__cvta_generic_to_shared(Bb);
    uint32_t dA0 = (lrow * 16 + 4 * (g0 ^ swz)) << 2;
    uint32_t dA1 = (lrow * 16 + 4 * (g1 ^ swz)) << 2;

    int am = m0 + lrow;
    int arow = (am < cnt) ? (idxArr ? idxArr[am] : am) : 0;
    arow = min(max(arow, 0), N_TOK - 1);
    int brow = min(n0 + lrow, N - 1);

    float acc[4][4][4];
#pragma unroll
    for (int mt = 0; mt < 4; mt++)
#pragma unroll
        for (int nt = 0; nt < 4; nt++)
#pragma unroll
            for (int e = 0; e < 4; e++) acc[mt][nt][e] = 0.0f;

    int gq = lane >> 2;
    int tq = lane & 3;

    int nk = K >> 5;
    // prologue: tiles 0 and 1 into slots 0 and 1
#pragma unroll
    for (int p = 0; p < 2; p++) {
        const uint32_t* ag = A  + ((size_t)p * 4096 + arow) * 16;
        const uint32_t* bg = Bw + ((size_t)p * N + brow) * 16;
        uint32_t so = (uint32_t)p * 8192;
        cp16(aShBase + so + dA0, ag + 4 * g0);
        cp16(aShBase + so + dA1, ag + 4 * g1);
        cp16(bShBase + so + dA0, bg + 4 * g0);
        cp16(bShBase + so + dA1, bg + 4 * g1);
        cp_commit();
    }

    int slot = 0;       // slot of tile kt
    for (int kt = 0; kt < nk; kt++) {
        cp_wait1();               // tile kt resident (kt+1 may be in flight)
        __syncthreads();          // all warps: tile kt visible, slot kt+2 free
        if (kt + 2 < nk) {
            int ns = slot + 2; if (ns >= 3) ns -= 3;
            const uint32_t* ag = A  + ((size_t)(kt + 2) * 4096 + arow) * 16;
            const uint32_t* bg = Bw + ((size_t)(kt + 2) * N + brow) * 16;
            uint32_t so = (uint32_t)ns * 8192;
            cp16(aShBase + so + dA0, ag + 4 * g0);
            cp16(aShBase + so + dA1, ag + 4 * g1);
            cp16(bShBase + so + dA0, bg + 4 * g0);
            cp16(bShBase + so + dA1, bg + 4 * g1);
        }
        cp_commit();              // unconditional: keeps group arithmetic fixed

        const uint32_t* As = Ab + slot * 2048;
        const uint32_t* Bs = Bb + slot * 2048;
        uint4 bf[4];
#pragma unroll
        for (int nt = 0; nt < 4; nt++) {
            int rb = wn * 32 + nt * 8 + gq;
            int gg = tq ^ ((rb >> 1) & 3);
            bf[nt] = *reinterpret_cast<const uint4*>(&Bs[rb * 16 + 4 * gg]);
        }
#pragma unroll
        for (int mt = 0; mt < 4; mt++) {
            int ra = wm * 64 + mt * 16 + gq;
            int gla = tq ^ ((ra >> 1) & 3);
            int glb = tq ^ (((ra + 8) >> 1) & 3);
            uint4 lo = *reinterpret_cast<const uint4*>(&As[ra * 16 + 4 * gla]);
            uint4 hi = *reinterpret_cast<const uint4*>(&As[(ra + 8) * 16 + 4 * glb]);
#pragma unroll
            for (int nt = 0; nt < 4; nt++)
                mma_f16(acc[mt][nt], lo.x, hi.x, lo.y, hi.y, bf[nt].x, bf[nt].y);
#pragma unroll
            for (int nt = 0; nt < 4; nt++)
                mma_f16(acc[mt][nt], lo.z, hi.z, lo.w, hi.w, bf[nt].z, bf[nt].w);
        }
        if (++slot == 3) slot = 0;
    }

    if (ce) {
        // ---- fused CE epilogue (spart aliases slot 0; see note above) ----
        float* labv = d_labv + phase * N_TOK;
#pragma unroll
        for (int mt = 0; mt < 4; mt++) {
#pragma unroll
            for (int h = 0; h < 2; h++) {
                int rloc = wm * 64 + mt * 16 + gq + h * 8;
                int m = m0 + rloc;
                bool ok = (m < cnt);
                int lab = ok ? labArr[m] : -1;
                float mx = -1e30f, sm = 0.f;
#pragma unroll
                for (int nt = 0; nt < 4; nt++) {
#pragma unroll
                    for (int e = 0; e < 2; e++) {
                        int col = n0 + wn * 32 + nt * 8 + tq * 2 + e;
                        if (col < N) {
                            float v = acc[mt][nt][h * 2 + e];
                            if (useBias) v += bias[col];
                            mx = fmaxf(mx, v);
                        }
                    }
                }
#pragma unroll
                for (int nt = 0; nt < 4; nt++) {
#pragma unroll
                    for (int e = 0; e < 2; e++) {
                        int col = n0 + wn * 32 + nt * 8 + tq * 2 + e;
                        if (col < N) {
                            float v = acc[mt][nt][h * 2 + e];
                            if (useBias) v += bias[col];
                            sm += __expf(v - mx);
                            if (ok && col == lab) labv[m] = v;
                        }
                    }
                }
#pragma unroll
                for (int off = 1; off <= 2; off <<= 1) {
                    float om = __shfl_xor_sync(0xffffffff, mx, off);
                    float os = __shfl_xor_sync(0xffffffff, sm, off);
                    ol_merge(mx, sm, om, os);
                }
                if (tq == 0) spart[rloc][wn] = make_float2(mx, sm);
            }
        }
        __syncthreads();
        if (tid < 128) {
            float mx = -1e30f, sm = 0.f;
#pragma unroll
            for (int w = 0; w < 4; w++) {
                float2 p = spart[tid][w];
                ol_merge(mx, sm, p.x, p.y);
            }
            int m = m0 + tid;
            if (m < cnt)
                d_part[((size_t)phase * N_TOK + m) * PT_STRIDE + blockIdx.x] =
                    make_float2(mx, sm);
        }
        return;
    }

    // ---- plain epilogue: write h in tiled fp16 layout ----
#pragma unroll
    for (int mt = 0; mt < 4; mt++) {
#pragma unroll
        for (int h = 0; h < 2; h++) {
            int r = m0 + wm * 64 + mt * 16 + gq + h * 8;
            if (r >= cnt) continue;
#pragma unroll
            for (int nt = 0; nt < 4; nt++) {
                int cb = n0 + wn * 32 + nt * 8 + tq * 2;
                int kt = cb >> 5;
                int p  = (cb & 31) >> 1;
                int s  = (p & 3) * 4 + (p >> 2);
                Cout[((size_t)kt * 4096 + r) * 16 + s] =
                    pack_h2(acc[mt][nt][h * 2 + 0], acc[mt][nt][h * 2 + 1]);
            }
        }
    }
}

// ---------------------------------------------------------------------------
__global__ __launch_bounds__(32)
void ce_merge() {
    int phase = blockIdx.y;
    int ntiles = (phase == 0) ? 16 : ((phase == 1) ? 63 : 313);
    int cnt    = (phase == 0) ? N_TOK : ((phase == 1) ? d_cnt0 : d_cnt1);
    if (cnt > N_TOK) cnt = N_TOK;
    int b = blockIdx.x;
    if (b >= cnt) return;
    int lane = threadIdx.x;

    const float2* base = d_part + ((size_t)phase * N_TOK + b) * PT_STRIDE;
    float mx = -1e30f, sm = 0.f;
    for (int t = lane; t < ntiles; t += 32) {
        float2 p = base[t];
        ol_merge(mx, sm, p.x, p.y);
    }
#pragma unroll
    for (int off = 16; off > 0; off >>= 1) {
        float om = __shfl_xor_sync(0xffffffff, mx, off);
        float os = __shfl_xor_sync(0xffffffff, sm, off);
        ol_merge(mx, sm, om, os);
    }
    if (lane == 0)
        d_nllv[phase * N_TOK + b] = logf(sm) + mx - d_labv[phase * N_TOK + b];
}

__global__ __launch_bounds__(1024)
void reduce_kernel(float* __restrict__ out) {
    __shared__ double s[1024];
    int c0 = min(d_cnt0, N_TOK), c1 = min(d_cnt1, N_TOK);
    double a = 0.0;
    for (int i = threadIdx.x; i < N_TOK; i += 1024) a += (double)d_nllv[i];
    for (int i = threadIdx.x; i < c0;    i += 1024) a += (double)d_nllv[N_TOK + i];
    for (int i = threadIdx.x; i < c1;    i += 1024) a += (double)d_nllv[2 * N_TOK + i];
    s[threadIdx.x] = a;
    __syncthreads();
#pragma unroll
    for (int k = 512; k > 0; k >>= 1) {
        if (threadIdx.x < k) s[threadIdx.x] += s[threadIdx.x + k];
        __syncthreads();
    }
    if (threadIdx.x == 0) out[0] = (float)(s[0] / (double)N_TOK);
}

// ---------------------------------------------------------------------------
extern "C" void kernel_launch(void* const* d_in, const int* in_sizes, int n_in,
                              void* d_out, int out_size) {
    const float* w_in   = (const float*)d_in[0];
    const int*   target = (const int*)d_in[1];
    const float* head_w = (const float*)d_in[2];
    const float* head_b = (const float*)d_in[3];
    const float* t0w1   = (const float*)d_in[4];
    const float* t0w2   = (const float*)d_in[5];
    const float* t1w1   = (const float*)d_in[6];
    const float* t1w2   = (const float*)d_in[7];
    float* out = (float*)d_out;

    init_kernel<<<1, 32>>>();
    gather_kernel<<<(N_TOK + 255) / 256, 256>>>(target);
    convert_kernel<<<(WTOT + 255) / 256, 256>>>(w_in, head_w, t0w1, t0w2,
                                                t1w1, t1w2);

    // stage A: head (fused CE) + t0s1 + t1s1
    gemm256<<<dim3(16, 32, 3), 256>>>(head_b, 0);
    // stage B: t1s2 (fused CE) + t0s2 (fused CE)
    gemm256<<<dim3(313, 32, 2), 256>>>(head_b, 1);

    ce_merge<<<dim3(N_TOK, 3), 32>>>();
    reduce_kernel<<<1, 1024>>>(out);
}

// round 11
// speedup vs baseline: 6.2198x; 1.0102x over previous
#include <cuda_runtime.h>
#include <cuda_fp16.h>
#include <cstdint>

// ---------------------------------------------------------------------------
// AdaptiveSoftmax — fp16 mma.sync, block 128x64 / warp 32x32 (3 blocks/SM),
// 3-stage cp.async ring, pre-tiled fp16 operands, fused-CE epilogue.
//   0: w_in [4096,1024] f32   1: target [4096] i32
//   2: head_w [2002,1024] f32 3: head_b [2002] f32
//   4: tail0_w1 [1024,1024]   5: tail0_w2 [8000,1024]
//   6: tail1_w1 [256,1024]    7: tail1_w2 [40000,256]
//   out: scalar f32 loss
// ---------------------------------------------------------------------------

#define N_TOK 4096
#define PT_STRIDE 632   // >= 625 N-tiles (tail1, 64-wide)

// fp16 operands in tiled layout: u32 idx = ((kt*R + row)*16 + slot)
// slot(p) = (p&3)*4 + (p>>2) for kpair p in k-tile of 32 halves.
__device__ __align__(16) uint32_t d_winh [2097152];
__device__ __align__(16) uint32_t d_hwh  [1025024];
__device__ __align__(16) uint32_t d_t0w1h[524288];
__device__ __align__(16) uint32_t d_t0w2h[4096000];
__device__ __align__(16) uint32_t d_t1w1h[131072];
__device__ __align__(16) uint32_t d_t1w2h[5120000];
__device__ __align__(16) uint32_t d_h0h  [2097152];   // R=4096, K=1024
__device__ __align__(16) uint32_t d_h1h  [524288];    // R=4096, K=256

__device__ __align__(16) float2 d_part[(size_t)3 * N_TOK * PT_STRIDE];
__device__ float d_labv[3 * N_TOK];
__device__ float d_nllv[3 * N_TOK];
__device__ int   d_labh[N_TOK];
__device__ int   d_lab0[N_TOK];
__device__ int   d_lab1[N_TOK];
__device__ int   d_idx0[N_TOK];
__device__ int   d_idx1[N_TOK];
__device__ int   d_cnt0;
__device__ int   d_cnt1;

// ---------------------------------------------------------------------------
__global__ void init_kernel() {
    if (threadIdx.x == 0) { d_cnt0 = 0; d_cnt1 = 0; }
}

__global__ void gather_kernel(const int* __restrict__ target) {
    int i = blockIdx.x * blockDim.x + threadIdx.x;
    if (i >= N_TOK) return;
    int t = target[i];
    int labh = t;
    if (t >= 2000 && t < 10000) {
        labh = 2000;
        int p = atomicAdd(&d_cnt0, 1);
        if (p < N_TOK) { d_idx0[p] = i; d_lab0[p] = t - 2000; }
    } else if (t >= 10000 && t < 50000) {
        labh = 2001;
        int p = atomicAdd(&d_cnt1, 1);
        if (p < N_TOK) { d_idx1[p] = i; d_lab1[p] = t - 10000; }
    }
    d_labh[i] = min(max(labh, 0), 2001);
}

// ---------------------------------------------------------------------------
__device__ __forceinline__ uint32_t pack_h2(float x, float y) {
    __half2 h = __floats2half2_rn(x, y);
    return *reinterpret_cast<uint32_t*>(&h);
}

#define W0 524288
#define W1 256256
#define W2 131072
#define W3 1024000
#define W4 32768
#define W5 1280000
#define WTOT (W0+W1+W2+W3+W4+W5)

__global__ __launch_bounds__(256)
void convert_kernel(const float* __restrict__ w_in, const float* __restrict__ head_w,
                    const float* __restrict__ t0w1, const float* __restrict__ t0w2,
                    const float* __restrict__ t1w1, const float* __restrict__ t1w2) {
    int i = blockIdx.x * 256 + threadIdx.x;
    if (i >= WTOT) return;
    const float* src; uint32_t* dst; int R, K, c = i;
    if (c < W0)              { src = w_in;   dst = d_winh;  R = 4096;  K = 1024; }
    else if ((c -= W0) < W1) { src = head_w; dst = d_hwh;   R = 2002;  K = 1024; }
    else if ((c -= W1) < W2) { src = t0w1;   dst = d_t0w1h; R = 1024;  K = 1024; }
    else if ((c -= W2) < W3) { src = t0w2;   dst = d_t0w2h; R = 8000;  K = 1024; }
    else if ((c -= W3) < W4) { src = t1w1;   dst = d_t1w1h; R = 256;   K = 1024; }
    else      { c -= W4;       src = t1w2;   dst = d_t1w2h; R = 40000; K = 256;  }
    int nrow4 = R * 4;
    int kt = c / nrow4;
    int rem = c - kt * nrow4;
    int r = rem >> 2, g = rem & 3;
    const float* s = src + (size_t)r * K + kt * 32 + 2 * g;
    uint4 o;
    o.x = pack_h2(s[0],  s[1]);
    o.y = pack_h2(s[8],  s[9]);
    o.z = pack_h2(s[16], s[17]);
    o.w = pack_h2(s[24], s[25]);
    reinterpret_cast<uint4*>(dst)[((size_t)kt * R + r) * 4 + g] = o;
}

// ---------------------------------------------------------------------------
__device__ __forceinline__ void mma_f16(float* d, uint32_t a0, uint32_t a1,
                                        uint32_t a2, uint32_t a3,
                                        uint32_t b0, uint32_t b1) {
    asm volatile(
        "mma.sync.aligned.m16n8k16.row.col.f32.f16.f16.f32 "
        "{%0,%1,%2,%3}, {%4,%5,%6,%7}, {%8,%9}, {%0,%1,%2,%3};"
        : "+f"(d[0]), "+f"(d[1]), "+f"(d[2]), "+f"(d[3])
        : "r"(a0), "r"(a1), "r"(a2), "r"(a3), "r"(b0), "r"(b1));
}

__device__ __forceinline__ void cp16(uint32_t saddr, const void* g) {
    asm volatile("cp.async.cg.shared.global [%0], [%1], 16;"
                 :: "r"(saddr), "l"(g));
}
__device__ __forceinline__ void cp_commit() {
    asm volatile("cp.async.commit_group;" ::: "memory");
}
__device__ __forceinline__ void cp_wait1() {
    asm volatile("cp.async.wait_group 1;" ::: "memory");
}

__device__ __forceinline__ void ol_merge(float& mx, float& sm, float om, float os) {
    float nm = fmaxf(mx, om);
    sm = sm * __expf(mx - nm) + os * __expf(om - nm);
    mx = nm;
}

// ---------------------------------------------------------------------------
// Unified GEMM: block 128x64x32, 256 thr, 8 warps (4m x 2n), warp 32x32.
// 3-stage cp.async ring, one __syncthreads per k-tile, 3 blocks/SM.
// CE spart aliases ring slot 0 (safe: nk in {32,8} -> last tile in slot 1).
// ---------------------------------------------------------------------------
__global__ __launch_bounds__(256, 3)
void gemm256(const float* __restrict__ bias, int stage) {
    int z = blockIdx.z;
    const uint32_t *A, *Bw;
    uint32_t* Cout = nullptr;
    const int* idxArr = nullptr;
    const int* labArr = nullptr;
    int N, K, cnt, xmax, ce = 0, phase = 0;
    bool useBias = false;
    if (stage == 0) {
        if (z == 0)      { A = d_winh; Bw = d_hwh;   N = 2002; K = 1024; cnt = N_TOK;
                           xmax = 32; ce = 1; phase = 0; labArr = d_labh; useBias = true; }
        else if (z == 1) { A = d_winh; Bw = d_t0w1h; N = 1024; K = 1024; cnt = d_cnt0;
                           xmax = 16; idxArr = d_idx0; Cout = d_h0h; }
        else             { A = d_winh; Bw = d_t1w1h; N = 256;  K = 1024; cnt = d_cnt1;
                           xmax = 4; idxArr = d_idx1; Cout = d_h1h; }
    } else {
        if (z == 0)      { A = d_h1h; Bw = d_t1w2h; N = 40000; K = 256;  cnt = d_cnt1;
                           xmax = 625; ce = 1; phase = 2; labArr = d_lab1; }
        else             { A = d_h0h; Bw = d_t0w2h; N = 8000;  K = 1024; cnt = d_cnt0;
                           xmax = 125; ce = 1; phase = 1; labArr = d_lab0; }
    }
    if ((int)blockIdx.x >= xmax) return;
    if (cnt > N_TOK) cnt = N_TOK;
    int m0 = blockIdx.y * 128;
    int n0 = blockIdx.x * 64;
    if (m0 >= cnt) return;

    // 3-slot ring: A slots 2048 u32 each at [s*2048], B slots 1024 u32 at
    // [6144 + s*1024]. Total 9216 u32 = 36 KB.
    __shared__ __align__(16) uint32_t Smem[9216];
    uint32_t* Ab = Smem;
    uint32_t* Bb = Smem + 6144;
    float2 (*spart)[2] = reinterpret_cast<float2(*)[2]>(Smem);  // aliases slot 0

    int tid  = threadIdx.x;
    int lane = tid & 31;
    int warp = tid >> 5;
    int wm = warp & 3;       // m offset wm*32
    int wn = warp >> 2;      // n offset wn*32

    // ---- A loader: 2 threads/row, 2 chunks each ----
    int lrow = tid >> 1;
    int hh   = tid & 1;
    int g0 = 2 * hh, g1 = 2 * hh + 1;
    int swzA = (lrow >> 1) & 3;
    uint32_t aShBase = (uint32_t)__cvta_generic_to_shared(Ab);
    uint32_t bShBase = (uint32_t)__cvta_generic_to_shared(Bb);
    uint32_t dA0 = (lrow * 16 + 4 * (g0 ^ swzA)) << 2;
    uint32_t dA1 = (lrow * 16 + 4 * (g1 ^ swzA)) << 2;
    // ---- B loader: 4 threads/row, 1 chunk each ----
    int brW = tid >> 2;
    int gB  = tid & 3;
    uint32_t dB = (brW * 16 + 4 * (gB ^ ((brW >> 1) & 3))) << 2;

    int am = m0 + lrow;
    int arow = (am < cnt) ? (idxArr ? idxArr[am] : am) : 0;
    arow = min(max(arow, 0), N_TOK - 1);
    int brow = min(n0 + brW, N - 1);

    float acc[2][4][4];
#pragma unroll
    for (int mt = 0; mt < 2; mt++)
#pragma unroll
        for (int nt = 0; nt < 4; nt++)
#pragma unroll
            for (int e = 0; e < 4; e++) acc[mt][nt][e] = 0.0f;

    int gq = lane >> 2;
    int tq = lane & 3;

    int nk = K >> 5;
    // prologue: tiles 0, 1 into slots 0, 1
#pragma unroll
    for (int p = 0; p < 2; p++) {
        const uint32_t* ag = A  + ((size_t)p * 4096 + arow) * 16;
        const uint32_t* bg = Bw + ((size_t)p * N + brow) * 16;
        cp16(aShBase + (uint32_t)p * 8192 + dA0, ag + 4 * g0);
        cp16(aShBase + (uint32_t)p * 8192 + dA1, ag + 4 * g1);
        cp16(bShBase + (uint32_t)p * 4096 + dB,  bg + 4 * gB);
        cp_commit();
    }

    int slot = 0;
    for (int kt = 0; kt < nk; kt++) {
        cp_wait1();
        __syncthreads();
        if (kt + 2 < nk) {
            int ns = slot + 2; if (ns >= 3) ns -= 3;
            const uint32_t* ag = A  + ((size_t)(kt + 2) * 4096 + arow) * 16;
            const uint32_t* bg = Bw + ((size_t)(kt + 2) * N + brow) * 16;
            cp16(aShBase + (uint32_t)ns * 8192 + dA0, ag + 4 * g0);
            cp16(aShBase + (uint32_t)ns * 8192 + dA1, ag + 4 * g1);
            cp16(bShBase + (uint32_t)ns * 4096 + dB,  bg + 4 * gB);
        }
        cp_commit();

        const uint32_t* As = Ab + slot * 2048;
        const uint32_t* Bs = Bb + slot * 1024;
        uint4 bf[4];
#pragma unroll
        for (int nt = 0; nt < 4; nt++) {
            int rb = wn * 32 + nt * 8 + gq;
            int gg = tq ^ ((rb >> 1) & 3);
            bf[nt] = *reinterpret_cast<const uint4*>(&Bs[rb * 16 + 4 * gg]);
        }
#pragma unroll
        for (int mt = 0; mt < 2; mt++) {
            int ra = wm * 32 + mt * 16 + gq;
            int gla = tq ^ ((ra >> 1) & 3);
            int glb = tq ^ (((ra + 8) >> 1) & 3);
            uint4 lo = *reinterpret_cast<const uint4*>(&As[ra * 16 + 4 * gla]);
            uint4 hi = *reinterpret_cast<const uint4*>(&As[(ra + 8) * 16 + 4 * glb]);
#pragma unroll
            for (int nt = 0; nt < 4; nt++)
                mma_f16(acc[mt][nt], lo.x, hi.x, lo.y, hi.y, bf[nt].x, bf[nt].y);
#pragma unroll
            for (int nt = 0; nt < 4; nt++)
                mma_f16(acc[mt][nt], lo.z, hi.z, lo.w, hi.w, bf[nt].z, bf[nt].w);
        }
        if (++slot == 3) slot = 0;
    }

    if (ce) {
        // ---- fused CE epilogue ----
        float* labv = d_labv + phase * N_TOK;
#pragma unroll
        for (int mt = 0; mt < 2; mt++) {
#pragma unroll
            for (int h = 0; h < 2; h++) {
                int rloc = wm * 32 + mt * 16 + gq + h * 8;
                int m = m0 + rloc;
                bool ok = (m < cnt);
                int lab = ok ? labArr[m] : -1;
                float mx = -1e30f, sm = 0.f;
#pragma unroll
                for (int nt = 0; nt < 4; nt++) {
#pragma unroll
                    for (int e = 0; e < 2; e++) {
                        int col = n0 + wn * 32 + nt * 8 + tq * 2 + e;
                        if (col < N) {
                            float v = acc[mt][nt][h * 2 + e];
                            if (useBias) v += bias[col];
                            mx = fmaxf(mx, v);
                        }
                    }
                }
#pragma unroll
                for (int nt = 0; nt < 4; nt++) {
#pragma unroll
                    for (int e = 0; e < 2; e++) {
                        int col = n0 + wn * 32 + nt * 8 + tq * 2 + e;
                        if (col < N) {
                            float v = acc[mt][nt][h * 2 + e];
                            if (useBias) v += bias[col];
                            sm += __expf(v - mx);
                            if (ok && col == lab) labv[m] = v;
                        }
                    }
                }
#pragma unroll
                for (int off = 1; off <= 2; off <<= 1) {
                    float om = __shfl_xor_sync(0xffffffff, mx, off);
                    float os = __shfl_xor_sync(0xffffffff, sm, off);
                    ol_merge(mx, sm, om, os);
                }
                if (tq == 0) spart[rloc][wn] = make_float2(mx, sm);
            }
        }
        __syncthreads();
        if (tid < 128) {
            float mx = -1e30f, sm = 0.f;
#pragma unroll
            for (int w = 0; w < 2; w++) {
                float2 p = spart[tid][w];
                ol_merge(mx, sm, p.x, p.y);
            }
            int m = m0 + tid;
            if (m < cnt)
                d_part[((size_t)phase * N_TOK + m) * PT_STRIDE + blockIdx.x] =
                    make_float2(mx, sm);
        }
        return;
    }

    // ---- plain epilogue: write h in tiled fp16 layout ----
#pragma unroll
    for (int mt = 0; mt < 2; mt++) {
#pragma unroll
        for (int h = 0; h < 2; h++) {
            int r = m0 + wm * 32 + mt * 16 + gq + h * 8;
            if (r >= cnt) continue;
#pragma unroll
            for (int nt = 0; nt < 4; nt++) {
                int cb = n0 + wn * 32 + nt * 8 + tq * 2;
                int kt = cb >> 5;
                int p  = (cb & 31) >> 1;
                int s  = (p & 3) * 4 + (p >> 2);
                Cout[((size_t)kt * 4096 + r) * 16 + s] =
                    pack_h2(acc[mt][nt][h * 2 + 0], acc[mt][nt][h * 2 + 1]);
            }
        }
    }
}

// ---------------------------------------------------------------------------
__global__ __launch_bounds__(32)
void ce_merge() {
    int phase = blockIdx.y;
    int ntiles = (phase == 0) ? 32 : ((phase == 1) ? 125 : 625);
    int cnt    = (phase == 0) ? N_TOK : ((phase == 1) ? d_cnt0 : d_cnt1);
    if (cnt > N_TOK) cnt = N_TOK;
    int b = blockIdx.x;
    if (b >= cnt) return;
    int lane = threadIdx.x;

    const float2* base = d_part + ((size_t)phase * N_TOK + b) * PT_STRIDE;
    float mx = -1e30f, sm = 0.f;
    for (int t = lane; t < ntiles; t += 32) {
        float2 p = base[t];
        ol_merge(mx, sm, p.x, p.y);
    }
#pragma unroll
    for (int off = 16; off > 0; off >>= 1) {
        float om = __shfl_xor_sync(0xffffffff, mx, off);
        float os = __shfl_xor_sync(0xffffffff, sm, off);
        ol_merge(mx, sm, om, os);
    }
    if (lane == 0)
        d_nllv[phase * N_TOK + b] = logf(sm) + mx - d_labv[phase * N_TOK + b];
}

__global__ __launch_bounds__(1024)
void reduce_kernel(float* __restrict__ out) {
    __shared__ double s[1024];
    int c0 = min(d_cnt0, N_TOK), c1 = min(d_cnt1, N_TOK);
    double a = 0.0;
    for (int i = threadIdx.x; i < N_TOK; i += 1024) a += (double)d_nllv[i];
    for (int i = threadIdx.x; i < c0;    i += 1024) a += (double)d_nllv[N_TOK + i];
    for (int i = threadIdx.x; i < c1;    i += 1024) a += (double)d_nllv[2 * N_TOK + i];
    s[threadIdx.x] = a;
    __syncthreads();
#pragma unroll
    for (int k = 512; k > 0; k >>= 1) {
        if (threadIdx.x < k) s[threadIdx.x] += s[threadIdx.x + k];
        __syncthreads();
    }
    if (threadIdx.x == 0) out[0] = (float)(s[0] / (double)N_TOK);
}

// ---------------------------------------------------------------------------
extern "C" void kernel_launch(void* const* d_in, const int* in_sizes, int n_in,
                              void* d_out, int out_size) {
    const float* w_in   = (const float*)d_in[0];
    const int*   target = (const int*)d_in[1];
    const float* head_w = (const float*)d_in[2];
    const float* head_b = (const float*)d_in[3];
    const float* t0w1   = (const float*)d_in[4];
    const float* t0w2   = (const float*)d_in[5];
    const float* t1w1   = (const float*)d_in[6];
    const float* t1w2   = (const float*)d_in[7];
    float* out = (float*)d_out;

    init_kernel<<<1, 32>>>();
    gather_kernel<<<(N_TOK + 255) / 256, 256>>>(target);
    convert_kernel<<<(WTOT + 255) / 256, 256>>>(w_in, head_w, t0w1, t0w2,
                                                t1w1, t1w2);

    // stage A: head (fused CE) + t0s1 + t1s1
    gemm256<<<dim3(32, 32, 3), 256>>>(head_b, 0);
    // stage B: t1s2 (fused CE) + t0s2 (fused CE)
    gemm256<<<dim3(625, 32, 2), 256>>>(head_b, 1);

    ce_merge<<<dim3(N_TOK, 3), 32>>>();
    reduce_kernel<<<1, 1024>>>(out);
}

// round 12
// speedup vs baseline: 6.2997x; 1.0128x over previous
#include <cuda_runtime.h>
#include <cuda_fp16.h>
#include <cstdint>

// ---------------------------------------------------------------------------
// AdaptiveSoftmax — fp16 mma.sync, block 128x64 / warp 32x32, 4-slot cp.async
// ring with x4-unrolled k-loop (compile-time smem slots), fused-CE epilogue.
//   0: w_in [4096,1024] f32   1: target [4096] i32
//   2: head_w [2002,1024] f32 3: head_b [2002] f32
//   4: tail0_w1 [1024,1024]   5: tail0_w2 [8000,1024]
//   6: tail1_w1 [256,1024]    7: tail1_w2 [40000,256]
//   out: scalar f32 loss
// ---------------------------------------------------------------------------

#define N_TOK 4096
#define PT_STRIDE 632   // >= 625 N-tiles (tail1, 64-wide)

// fp16 operands in tiled layout: u32 idx = ((kt*R + row)*16 + slot)
// slot(p) = (p&3)*4 + (p>>2) for kpair p in k-tile of 32 halves.
__device__ __align__(16) uint32_t d_winh [2097152];
__device__ __align__(16) uint32_t d_hwh  [1025024];
__device__ __align__(16) uint32_t d_t0w1h[524288];
__device__ __align__(16) uint32_t d_t0w2h[4096000];
__device__ __align__(16) uint32_t d_t1w1h[131072];
__device__ __align__(16) uint32_t d_t1w2h[5120000];
__device__ __align__(16) uint32_t d_h0h  [2097152];   // R=4096, K=1024
__device__ __align__(16) uint32_t d_h1h  [524288];    // R=4096, K=256

__device__ __align__(16) float2 d_part[(size_t)3 * N_TOK * PT_STRIDE];
__device__ float d_labv[3 * N_TOK];
__device__ float d_nllv[3 * N_TOK];
__device__ int   d_labh[N_TOK];
__device__ int   d_lab0[N_TOK];
__device__ int   d_lab1[N_TOK];
__device__ int   d_idx0[N_TOK];
__device__ int   d_idx1[N_TOK];
__device__ int   d_cnt0;
__device__ int   d_cnt1;

// ---------------------------------------------------------------------------
__global__ void init_kernel() {
    if (threadIdx.x == 0) { d_cnt0 = 0; d_cnt1 = 0; }
}

__global__ void gather_kernel(const int* __restrict__ target) {
    int i = blockIdx.x * blockDim.x + threadIdx.x;
    if (i >= N_TOK) return;
    int t = target[i];
    int labh = t;
    if (t >= 2000 && t < 10000) {
        labh = 2000;
        int p = atomicAdd(&d_cnt0, 1);
        if (p < N_TOK) { d_idx0[p] = i; d_lab0[p] = t - 2000; }
    } else if (t >= 10000 && t < 50000) {
        labh = 2001;
        int p = atomicAdd(&d_cnt1, 1);
        if (p < N_TOK) { d_idx1[p] = i; d_lab1[p] = t - 10000; }
    }
    d_labh[i] = min(max(labh, 0), 2001);
}

// ---------------------------------------------------------------------------
__device__ __forceinline__ uint32_t pack_h2(float x, float y) {
    __half2 h = __floats2half2_rn(x, y);
    return *reinterpret_cast<uint32_t*>(&h);
}

#define W0 524288
#define W1 256256
#define W2 131072
#define W3 1024000
#define W4 32768
#define W5 1280000
#define WTOT (W0+W1+W2+W3+W4+W5)

__global__ __launch_bounds__(256)
void convert_kernel(const float* __restrict__ w_in, const float* __restrict__ head_w,
                    const float* __restrict__ t0w1, const float* __restrict__ t0w2,
                    const float* __restrict__ t1w1, const float* __restrict__ t1w2) {
    int i = blockIdx.x * 256 + threadIdx.x;
    if (i >= WTOT) return;
    const float* src; uint32_t* dst; int R, K, c = i;
    if (c < W0)              { src = w_in;   dst = d_winh;  R = 4096;  K = 1024; }
    else if ((c -= W0) < W1) { src = head_w; dst = d_hwh;   R = 2002;  K = 1024; }
    else if ((c -= W1) < W2) { src = t0w1;   dst = d_t0w1h; R = 1024;  K = 1024; }
    else if ((c -= W2) < W3) { src = t0w2;   dst = d_t0w2h; R = 8000;  K = 1024; }
    else if ((c -= W3) < W4) { src = t1w1;   dst = d_t1w1h; R = 256;   K = 1024; }
    else      { c -= W4;       src = t1w2;   dst = d_t1w2h; R = 40000; K = 256;  }
    int nrow4 = R * 4;
    int kt = c / nrow4;
    int rem = c - kt * nrow4;
    int r = rem >> 2, g = rem & 3;
    const float* s = src + (size_t)r * K + kt * 32 + 2 * g;
    uint4 o;
    o.x = pack_h2(s[0],  s[1]);
    o.y = pack_h2(s[8],  s[9]);
    o.z = pack_h2(s[16], s[17]);
    o.w = pack_h2(s[24], s[25]);
    reinterpret_cast<uint4*>(dst)[((size_t)kt * R + r) * 4 + g] = o;
}

// ---------------------------------------------------------------------------
__device__ __forceinline__ void mma_f16(float* d, uint32_t a0, uint32_t a1,
                                        uint32_t a2, uint32_t a3,
                                        uint32_t b0, uint32_t b1) {
    asm volatile(
        "mma.sync.aligned.m16n8k16.row.col.f32.f16.f16.f32 "
        "{%0,%1,%2,%3}, {%4,%5,%6,%7}, {%8,%9}, {%0,%1,%2,%3};"
        : "+f"(d[0]), "+f"(d[1]), "+f"(d[2]), "+f"(d[3])
        : "r"(a0), "r"(a1), "r"(a2), "r"(a3), "r"(b0), "r"(b1));
}

__device__ __forceinline__ void cp16(uint32_t saddr, const void* g) {
    asm volatile("cp.async.cg.shared.global [%0], [%1], 16;"
                 :: "r"(saddr), "l"(g));
}
__device__ __forceinline__ void cp_commit() {
    asm volatile("cp.async.commit_group;" ::: "memory");
}
__device__ __forceinline__ void cp_wait2() {
    asm volatile("cp.async.wait_group 2;" ::: "memory");
}

__device__ __forceinline__ void ol_merge(float& mx, float& sm, float om, float os) {
    float nm = fmaxf(mx, om);
    sm = sm * __expf(mx - nm) + os * __expf(om - nm);
    mx = nm;
}

// ---------------------------------------------------------------------------
// Unified GEMM: block 128x64x32, 256 thr, 8 warps (4m x 2n), warp 32x32.
// 4-slot ring (A 4x2048 u32, B 4x1024 u32 = 48KB), k-loop unrolled x4 so all
// smem addresses are base+immediate. 3 tiles in flight (wait_group 2).
// CE spart aliases slot 0 (safe: nk%4==0 -> last tile in slot 3).
// ---------------------------------------------------------------------------
__global__ __launch_bounds__(256, 3)
void gemm256(const float* __restrict__ bias, int stage) {
    int z = blockIdx.z;
    const uint32_t *A, *Bw;
    uint32_t* Cout = nullptr;
    const int* idxArr = nullptr;
    const int* labArr = nullptr;
    int N, K, cnt, xmax, ce = 0, phase = 0;
    bool useBias = false;
    if (stage == 0) {
        if (z == 0)      { A = d_winh; Bw = d_hwh;   N = 2002; K = 1024; cnt = N_TOK;
                           xmax = 32; ce = 1; phase = 0; labArr = d_labh; useBias = true; }
        else if (z == 1) { A = d_winh; Bw = d_t0w1h; N = 1024; K = 1024; cnt = d_cnt0;
                           xmax = 16; idxArr = d_idx0; Cout = d_h0h; }
        else             { A = d_winh; Bw = d_t1w1h; N = 256;  K = 1024; cnt = d_cnt1;
                           xmax = 4; idxArr = d_idx1; Cout = d_h1h; }
    } else {
        if (z == 0)      { A = d_h1h; Bw = d_t1w2h; N = 40000; K = 256;  cnt = d_cnt1;
                           xmax = 625; ce = 1; phase = 2; labArr = d_lab1; }
        else             { A = d_h0h; Bw = d_t0w2h; N = 8000;  K = 1024; cnt = d_cnt0;
                           xmax = 125; ce = 1; phase = 1; labArr = d_lab0; }
    }
    if ((int)blockIdx.x >= xmax) return;
    if (cnt > N_TOK) cnt = N_TOK;
    int m0 = blockIdx.y * 128;
    int n0 = blockIdx.x * 64;
    if (m0 >= cnt) return;

    // 4-slot ring: A slots 2048 u32 at [s*2048], B slots 1024 u32 at
    // [8192 + s*1024]. Total 12288 u32 = 48KB.
    __shared__ __align__(16) uint32_t Smem[12288];
    uint32_t* Ab = Smem;
    uint32_t* Bb = Smem + 8192;
    float2 (*spart)[2] = reinterpret_cast<float2(*)[2]>(Smem);  // aliases slot 0

    int tid  = threadIdx.x;
    int lane = tid & 31;
    int warp = tid >> 5;
    int wm = warp & 3;       // m offset wm*32
    int wn = warp >> 2;      // n offset wn*32

    // ---- A loader: 2 threads/row, 2 chunks each ----
    int lrow = tid >> 1;
    int hh   = tid & 1;
    int g0 = 2 * hh, g1 = 2 * hh + 1;
    int swzA = (lrow >> 1) & 3;
    uint32_t aShBase = (uint32_t)__cvta_generic_to_shared(Ab);
    uint32_t bShBase = (uint32_t)__cvta_generic_to_shared(Bb);
    uint32_t dA0 = (lrow * 16 + 4 * (g0 ^ swzA)) << 2;
    uint32_t dA1 = (lrow * 16 + 4 * (g1 ^ swzA)) << 2;
    // ---- B loader: 4 threads/row, 1 chunk each ----
    int brW = tid >> 2;
    int gB  = tid & 3;
    uint32_t dB = (brW * 16 + 4 * (gB ^ ((brW >> 1) & 3))) << 2;

    int am = m0 + lrow;
    int arow = (am < cnt) ? (idxArr ? idxArr[am] : am) : 0;
    arow = min(max(arow, 0), N_TOK - 1);
    int brow = min(n0 + brW, N - 1);

    float acc[2][4][4];
#pragma unroll
    for (int mt = 0; mt < 2; mt++)
#pragma unroll
        for (int nt = 0; nt < 4; nt++)
#pragma unroll
            for (int e = 0; e < 4; e++) acc[mt][nt][e] = 0.0f;

    int gq = lane >> 2;
    int tq = lane & 3;

    const size_t aStep = 4096 * 16;          // u32 per A k-tile
    const size_t bStep = (size_t)N * 16;     // u32 per B k-tile

    int nk = K >> 5;                         // 32 or 8 (divisible by 4)
    const uint32_t* agp = A  + (size_t)arow * 16;
    const uint32_t* bgp = Bw + (size_t)brow * 16;

    // prologue: tiles 0,1,2 into slots 0,1,2
#pragma unroll
    for (int p = 0; p < 3; p++) {
        cp16(aShBase + (uint32_t)p * 8192 + dA0, agp + 4 * g0);
        cp16(aShBase + (uint32_t)p * 8192 + dA1, agp + 4 * g1);
        cp16(bShBase + (uint32_t)p * 4096 + dB,  bgp + 4 * gB);
        cp_commit();
        agp += aStep; bgp += bStep;
    }
    // agp/bgp now point at tile 3 (next to prefetch)

    for (int kt0 = 0; kt0 < nk; kt0 += 4) {
#pragma unroll
        for (int u = 0; u < 4; u++) {
            int kt = kt0 + u;
            cp_wait2();
            __syncthreads();
            if (kt + 3 < nk) {
                const uint32_t so = (uint32_t)(((u + 3) & 3));
                cp16(aShBase + so * 8192 + dA0, agp + 4 * g0);
                cp16(aShBase + so * 8192 + dA1, agp + 4 * g1);
                cp16(bShBase + so * 4096 + dB,  bgp + 4 * gB);
                agp += aStep; bgp += bStep;
            }
            cp_commit();

            const uint32_t* As = Ab + u * 2048;   // compile-time slot
            const uint32_t* Bs = Bb + u * 1024;
            uint4 bf[4];
#pragma unroll
            for (int nt = 0; nt < 4; nt++) {
                int rb = wn * 32 + nt * 8 + gq;
                int gg = tq ^ ((rb >> 1) & 3);
                bf[nt] = *reinterpret_cast<const uint4*>(&Bs[rb * 16 + 4 * gg]);
            }
#pragma unroll
            for (int mt = 0; mt < 2; mt++) {
                int ra = wm * 32 + mt * 16 + gq;
                int gla = tq ^ ((ra >> 1) & 3);
                int glb = tq ^ (((ra + 8) >> 1) & 3);
                uint4 lo = *reinterpret_cast<const uint4*>(&As[ra * 16 + 4 * gla]);
                uint4 hi = *reinterpret_cast<const uint4*>(&As[(ra + 8) * 16 + 4 * glb]);
#pragma unroll
                for (int nt = 0; nt < 4; nt++)
                    mma_f16(acc[mt][nt], lo.x, hi.x, lo.y, hi.y, bf[nt].x, bf[nt].y);
#pragma unroll
                for (int nt = 0; nt < 4; nt++)
                    mma_f16(acc[mt][nt], lo.z, hi.z, lo.w, hi.w, bf[nt].z, bf[nt].w);
            }
        }
    }

    if (ce) {
        // ---- fused CE epilogue ----
        float* labv = d_labv + phase * N_TOK;
#pragma unroll
        for (int mt = 0; mt < 2; mt++) {
#pragma unroll
            for (int h = 0; h < 2; h++) {
                int rloc = wm * 32 + mt * 16 + gq + h * 8;
                int m = m0 + rloc;
                bool ok = (m < cnt);
                int lab = ok ? labArr[m] : -1;
                float mx = -1e30f, sm = 0.f;
#pragma unroll
                for (int nt = 0; nt < 4; nt++) {
#pragma unroll
                    for (int e = 0; e < 2; e++) {
                        int col = n0 + wn * 32 + nt * 8 + tq * 2 + e;
                        if (col < N) {
                            float v = acc[mt][nt][h * 2 + e];
                            if (useBias) v += bias[col];
                            mx = fmaxf(mx, v);
                        }
                    }
                }
#pragma unroll
                for (int nt = 0; nt < 4; nt++) {
#pragma unroll
                    for (int e = 0; e < 2; e++) {
                        int col = n0 + wn * 32 + nt * 8 + tq * 2 + e;
                        if (col < N) {
                            float v = acc[mt][nt][h * 2 + e];
                            if (useBias) v += bias[col];
                            sm += __expf(v - mx);
                            if (ok && col == lab) labv[m] = v;
                        }
                    }
                }
#pragma unroll
                for (int off = 1; off <= 2; off <<= 1) {
                    float om = __shfl_xor_sync(0xffffffff, mx, off);
                    float os = __shfl_xor_sync(0xffffffff, sm, off);
                    ol_merge(mx, sm, om, os);
                }
                if (tq == 0) spart[rloc][wn] = make_float2(mx, sm);
            }
        }
        __syncthreads();
        if (tid < 128) {
            float mx = -1e30f, sm = 0.f;
#pragma unroll
            for (int w = 0; w < 2; w++) {
                float2 p = spart[tid][w];
                ol_merge(mx, sm, p.x, p.y);
            }
            int m = m0 + tid;
            if (m < cnt)
                d_part[((size_t)phase * N_TOK + m) * PT_STRIDE + blockIdx.x] =
                    make_float2(mx, sm);
        }
        return;
    }

    // ---- plain epilogue: write h in tiled fp16 layout ----
#pragma unroll
    for (int mt = 0; mt < 2; mt++) {
#pragma unroll
        for (int h = 0; h < 2; h++) {
            int r = m0 + wm * 32 + mt * 16 + gq + h * 8;
            if (r >= cnt) continue;
#pragma unroll
            for (int nt = 0; nt < 4; nt++) {
                int cb = n0 + wn * 32 + nt * 8 + tq * 2;
                int kt = cb >> 5;
                int p  = (cb & 31) >> 1;
                int s  = (p & 3) * 4 + (p >> 2);
                Cout[((size_t)kt * 4096 + r) * 16 + s] =
                    pack_h2(acc[mt][nt][h * 2 + 0], acc[mt][nt][h * 2 + 1]);
            }
        }
    }
}

// ---------------------------------------------------------------------------
__global__ __launch_bounds__(32)
void ce_merge() {
    int phase = blockIdx.y;
    int ntiles = (phase == 0) ? 32 : ((phase == 1) ? 125 : 625);
    int cnt    = (phase == 0) ? N_TOK : ((phase == 1) ? d_cnt0 : d_cnt1);
    if (cnt > N_TOK) cnt = N_TOK;
    int b = blockIdx.x;
    if (b >= cnt) return;
    int lane = threadIdx.x;

    const float2* base = d_part + ((size_t)phase * N_TOK + b) * PT_STRIDE;
    float mx = -1e30f, sm = 0.f;
    for (int t = lane; t < ntiles; t += 32) {
        float2 p = base[t];
        ol_merge(mx, sm, p.x, p.y);
    }
#pragma unroll
    for (int off = 16; off > 0; off >>= 1) {
        float om = __shfl_xor_sync(0xffffffff, mx, off);
        float os = __shfl_xor_sync(0xffffffff, sm, off);
        ol_merge(mx, sm, om, os);
    }
    if (lane == 0)
        d_nllv[phase * N_TOK + b] = logf(sm) + mx - d_labv[phase * N_TOK + b];
}

__global__ __launch_bounds__(1024)
void reduce_kernel(float* __restrict__ out) {
    __shared__ double s[1024];
    int c0 = min(d_cnt0, N_TOK), c1 = min(d_cnt1, N_TOK);
    double a = 0.0;
    for (int i = threadIdx.x; i < N_TOK; i += 1024) a += (double)d_nllv[i];
    for (int i = threadIdx.x; i < c0;    i += 1024) a += (double)d_nllv[N_TOK + i];
    for (int i = threadIdx.x; i < c1;    i += 1024) a += (double)d_nllv[2 * N_TOK + i];
    s[threadIdx.x] = a;
    __syncthreads();
#pragma unroll
    for (int k = 512; k > 0; k >>= 1) {
        if (threadIdx.x < k) s[threadIdx.x] += s[threadIdx.x + k];
        __syncthreads();
    }
    if (threadIdx.x == 0) out[0] = (float)(s[0] / (double)N_TOK);
}

// ---------------------------------------------------------------------------
extern "C" void kernel_launch(void* const* d_in, const int* in_sizes, int n_in,
                              void* d_out, int out_size) {
    const float* w_in   = (const float*)d_in[0];
    const int*   target = (const int*)d_in[1];
    const float* head_w = (const float*)d_in[2];
    const float* head_b = (const float*)d_in[3];
    const float* t0w1   = (const float*)d_in[4];
    const float* t0w2   = (const float*)d_in[5];
    const float* t1w1   = (const float*)d_in[6];
    const float* t1w2   = (const float*)d_in[7];
    float* out = (float*)d_out;

    init_kernel<<<1, 32>>>();
    gather_kernel<<<(N_TOK + 255) / 256, 256>>>(target);
    convert_kernel<<<(WTOT + 255) / 256, 256>>>(w_in, head_w, t0w1, t0w2,
                                                t1w1, t1w2);

    // stage A: head (fused CE) + t0s1 + t1s1
    gemm256<<<dim3(32, 32, 3), 256>>>(head_b, 0);
    // stage B: t1s2 (fused CE) + t0s2 (fused CE)
    gemm256<<<dim3(625, 32, 2), 256>>>(head_b, 1);

    ce_merge<<<dim3(N_TOK, 3), 32>>>();
    reduce_kernel<<<1, 1024>>>(out);
}